// round 2
// baseline (speedup 1.0000x reference)
#include <cuda_runtime.h>
#include <cuda_bf16.h>
#include <math.h>

// Problem constants
#define NFEAT    128
#define NHID     256
#define HEADS    4
#define DH       64
#define N_NODES  32768
#define N_EDGES  524288
#define NGRAPHS  64
#define NPG      512            // nodes per graph
#define QKVDIM   768

// ---------------------------------------------------------------------------
// Scratch (static device globals; no allocation allowed)
// ---------------------------------------------------------------------------
__device__ float g_h1[N_NODES * NHID];
__device__ float g_h2[N_NODES * NHID];
__device__ float g_inc[N_NODES * NHID];        // x0, then += scatter => inception
__device__ float g_qkv[N_NODES * QKVDIM];
__device__ float g_ctx[N_NODES * NHID];
__device__ float g_y[N_NODES * NHID];          // attended (post out_proj)
__device__ float g_wqkvT[NHID * QKVDIM];       // in_proj_w^T  [256][768]
__device__ float g_woT[NHID * NHID];           // out_proj_w^T [256][256]

// ---------------------------------------------------------------------------
// Small transpose: out[c][rows] = in[r][cols]
// ---------------------------------------------------------------------------
__global__ void transpose_kernel(const float* __restrict__ in, float* __restrict__ out,
                                 int rows, int cols) {
    int idx = blockIdx.x * 256 + threadIdx.x;
    if (idx < rows * cols) {
        int r = idx / cols, c = idx % cols;
        out[c * rows + r] = in[idx];
    }
}

// ---------------------------------------------------------------------------
// SGEMM (NN): C[M,N] = A[M,K] @ B[K,N] (+ bias[N])
// BM=128, BN=128, BK=16, 256 threads, 8x8 per thread.
// M % 128 == 0, N % 128 == 0, K % 16 == 0 (all shapes here satisfy this).
// ---------------------------------------------------------------------------
#define BM 128
#define BN 128
#define BK 16

__global__ __launch_bounds__(256) void sgemm_nn(
    const float* __restrict__ A, const float* __restrict__ B,
    const float* __restrict__ bias, float* __restrict__ C,
    int M, int N, int K)
{
    __shared__ float As[BK][BM];
    __shared__ float Bs[BK][BN];

    const int tid  = threadIdx.x;
    const int row0 = blockIdx.y * BM;
    const int col0 = blockIdx.x * BN;
    const int tm   = tid / 16;          // 0..15 -> 8 rows each
    const int tn   = tid % 16;          // 0..15 -> 8 cols each

    // A load mapping: 2x float4 per thread
    const int arow = tid >> 1;          // 0..127
    const int ak   = (tid & 1) * 8;     // 0 or 8
    // B load mapping: 2x float4 per thread
    const int brow = tid >> 4;          // 0..15
    const int bcol = (tid & 15) * 8;    // 0..120

    float acc[8][8];
    #pragma unroll
    for (int i = 0; i < 8; i++)
        #pragma unroll
        for (int j = 0; j < 8; j++) acc[i][j] = 0.f;

    const float* Aptr = A + (size_t)(row0 + arow) * K;

    for (int k0 = 0; k0 < K; k0 += BK) {
        float4 a0 = *(const float4*)&Aptr[k0 + ak];
        float4 a1 = *(const float4*)&Aptr[k0 + ak + 4];
        As[ak + 0][arow] = a0.x; As[ak + 1][arow] = a0.y;
        As[ak + 2][arow] = a0.z; As[ak + 3][arow] = a0.w;
        As[ak + 4][arow] = a1.x; As[ak + 5][arow] = a1.y;
        As[ak + 6][arow] = a1.z; As[ak + 7][arow] = a1.w;

        const float* Bptr = B + (size_t)(k0 + brow) * N + col0 + bcol;
        *(float4*)&Bs[brow][bcol]     = *(const float4*)&Bptr[0];
        *(float4*)&Bs[brow][bcol + 4] = *(const float4*)&Bptr[4];

        __syncthreads();

        #pragma unroll
        for (int kk = 0; kk < BK; kk++) {
            float a[8], b[8];
            *(float4*)&a[0] = *(const float4*)&As[kk][tm * 8];
            *(float4*)&a[4] = *(const float4*)&As[kk][tm * 8 + 4];
            *(float4*)&b[0] = *(const float4*)&Bs[kk][tn * 8];
            *(float4*)&b[4] = *(const float4*)&Bs[kk][tn * 8 + 4];
            #pragma unroll
            for (int i = 0; i < 8; i++)
                #pragma unroll
                for (int j = 0; j < 8; j++)
                    acc[i][j] += a[i] * b[j];
        }
        __syncthreads();
    }

    float bv[8];
    #pragma unroll
    for (int j = 0; j < 8; j++)
        bv[j] = bias ? bias[col0 + tn * 8 + j] : 0.f;

    #pragma unroll
    for (int i = 0; i < 8; i++) {
        float* cp = C + (size_t)(row0 + tm * 8 + i) * N + col0 + tn * 8;
        float4 o0 = make_float4(acc[i][0] + bv[0], acc[i][1] + bv[1],
                                acc[i][2] + bv[2], acc[i][3] + bv[3]);
        float4 o1 = make_float4(acc[i][4] + bv[4], acc[i][5] + bv[5],
                                acc[i][6] + bv[6], acc[i][7] + bv[7]);
        *(float4*)&cp[0] = o0;
        *(float4*)&cp[4] = o1;
    }
}

// ---------------------------------------------------------------------------
// Edge scatter: out[dst] += ea[e] * h[src]   (64 threads / edge, float4 lanes)
// ---------------------------------------------------------------------------
__global__ __launch_bounds__(256) void scatter_kernel(
    const int* __restrict__ ei, const float* __restrict__ ea,
    const float* __restrict__ h, float* __restrict__ out, int n_edges)
{
    int t = blockIdx.x * 256 + threadIdx.x;
    int e = t >> 6;
    if (e >= n_edges) return;
    int lane = (t & 63) * 4;
    int src = ei[e];
    int dst = ei[n_edges + e];
    float a = ea[e];
    float4 m = *(const float4*)&h[(size_t)src * NHID + lane];
    float* o = &out[(size_t)dst * NHID + lane];
    atomicAdd(o + 0, a * m.x);
    atomicAdd(o + 1, a * m.y);
    atomicAdd(o + 2, a * m.z);
    atomicAdd(o + 3, a * m.w);
}

// ---------------------------------------------------------------------------
// Per-graph multi-head attention (flash-style, online softmax).
// Block = (qtile 0..3, head 0..3, graph 0..63). 128 threads = 128 query rows.
// q row + accumulator in registers; 64-key K/V tiles in smem (broadcast LDS).
// Writes ctx [N_NODES, NHID] (pre-out_proj).
// ---------------------------------------------------------------------------
__global__ __launch_bounds__(128) void attn_kernel(
    const float* __restrict__ qkv, float* __restrict__ ctx)
{
    const int qt = blockIdx.x;
    const int h  = blockIdx.y;
    const int g  = blockIdx.z;
    const int tid = threadIdx.x;

    __shared__ float Ks[64][DH];
    __shared__ float Vs[64][DH];

    const int qrow = g * NPG + qt * 128 + tid;
    const float* qp = &qkv[(size_t)qrow * QKVDIM + h * DH];

    float q[DH];
    #pragma unroll
    for (int i = 0; i < 16; i++) {
        float4 v = *(const float4*)&qp[i * 4];
        q[4 * i + 0] = v.x * 0.125f;
        q[4 * i + 1] = v.y * 0.125f;
        q[4 * i + 2] = v.z * 0.125f;
        q[4 * i + 3] = v.w * 0.125f;
    }

    float m = -1e30f, l = 0.f;
    float acc[DH];
    #pragma unroll
    for (int d = 0; d < DH; d++) acc[d] = 0.f;

    for (int kt = 0; kt < NPG / 64; kt++) {
        __syncthreads();
        #pragma unroll
        for (int i = 0; i < 8; i++) {
            int idx = tid + i * 128;      // 0..1023
            int j   = idx >> 4;           // key in tile
            int dd  = (idx & 15) * 4;
            int krow = g * NPG + kt * 64 + j;
            const float* base = &qkv[(size_t)krow * QKVDIM];
            *(float4*)&Ks[j][dd] = *(const float4*)&base[NHID + h * DH + dd];
            *(float4*)&Vs[j][dd] = *(const float4*)&base[2 * NHID + h * DH + dd];
        }
        __syncthreads();

        for (int j = 0; j < 64; j++) {
            float s = 0.f;
            #pragma unroll
            for (int d4 = 0; d4 < 16; d4++) {
                float4 kv = *(const float4*)&Ks[j][d4 * 4];
                s += q[d4 * 4 + 0] * kv.x + q[d4 * 4 + 1] * kv.y
                   + q[d4 * 4 + 2] * kv.z + q[d4 * 4 + 3] * kv.w;
            }
            float p;
            if (s <= m) {
                p = __expf(s - m);
            } else {
                float scale = __expf(m - s);
                l *= scale;
                #pragma unroll
                for (int d = 0; d < DH; d++) acc[d] *= scale;
                m = s;
                p = 1.0f;
            }
            l += p;
            #pragma unroll
            for (int d4 = 0; d4 < 16; d4++) {
                float4 vv = *(const float4*)&Vs[j][d4 * 4];
                acc[d4 * 4 + 0] += p * vv.x;
                acc[d4 * 4 + 1] += p * vv.y;
                acc[d4 * 4 + 2] += p * vv.z;
                acc[d4 * 4 + 3] += p * vv.w;
            }
        }
    }

    float inv = 1.0f / l;
    float* op = &ctx[(size_t)qrow * NHID + h * DH];
    #pragma unroll
    for (int d4 = 0; d4 < 16; d4++) {
        float4 o = make_float4(acc[d4 * 4 + 0] * inv, acc[d4 * 4 + 1] * inv,
                               acc[d4 * 4 + 2] * inv, acc[d4 * 4 + 3] * inv);
        *(float4*)&op[d4 * 4] = o;
    }
}

// ---------------------------------------------------------------------------
// out = LayerNorm(inception + attended) * gamma + beta ; one block per row
// ---------------------------------------------------------------------------
__global__ __launch_bounds__(256) void add_ln_kernel(
    const float* __restrict__ inc, const float* __restrict__ y,
    const float* __restrict__ gamma, const float* __restrict__ beta,
    float* __restrict__ out)
{
    const int row = blockIdx.x;
    const int tid = threadIdx.x;
    const size_t base = (size_t)row * NHID;

    float v = inc[base + tid] + y[base + tid];

    float s1 = v, s2 = v * v;
    #pragma unroll
    for (int o = 16; o; o >>= 1) {
        s1 += __shfl_xor_sync(0xFFFFFFFFu, s1, o);
        s2 += __shfl_xor_sync(0xFFFFFFFFu, s2, o);
    }
    __shared__ float r1[8], r2[8];
    if ((tid & 31) == 0) { r1[tid >> 5] = s1; r2[tid >> 5] = s2; }
    __syncthreads();
    float t1 = 0.f, t2 = 0.f;
    #pragma unroll
    for (int i = 0; i < 8; i++) { t1 += r1[i]; t2 += r2[i]; }

    float mu  = t1 * (1.0f / NHID);
    float var = t2 * (1.0f / NHID) - mu * mu;
    float rs  = rsqrtf(var + 1e-5f);
    out[base + tid] = (v - mu) * rs * gamma[tid] + beta[tid];
}

// ---------------------------------------------------------------------------
// Launch
// ---------------------------------------------------------------------------
extern "C" void kernel_launch(void* const* d_in, const int* in_sizes, int n_in,
                              void* d_out, int out_size)
{
    const float* x     = (const float*)d_in[0];
    const float* ea1   = (const float*)d_in[1];
    const float* ea2   = (const float*)d_in[2];
    const float* ln_w  = (const float*)d_in[3];
    const float* w1    = (const float*)d_in[4];
    const float* w2    = (const float*)d_in[5];
    const float* inw   = (const float*)d_in[6];   // [768,256]
    const float* inb   = (const float*)d_in[7];   // [768]
    const float* outw  = (const float*)d_in[8];   // [256,256]
    const float* outb  = (const float*)d_in[9];   // [256]
    const float* gamma = (const float*)d_in[10];
    const float* beta  = (const float*)d_in[11];
    const int*   ei1   = (const int*)d_in[12];
    const int*   ei2   = (const int*)d_in[13];
    float* out = (float*)d_out;

    const int n_edges = in_sizes[1];              // 524288

    float *p_h1, *p_h2, *p_inc, *p_qkv, *p_ctx, *p_y, *p_wqkvT, *p_woT;
    cudaGetSymbolAddress((void**)&p_h1, g_h1);
    cudaGetSymbolAddress((void**)&p_h2, g_h2);
    cudaGetSymbolAddress((void**)&p_inc, g_inc);
    cudaGetSymbolAddress((void**)&p_qkv, g_qkv);
    cudaGetSymbolAddress((void**)&p_ctx, g_ctx);
    cudaGetSymbolAddress((void**)&p_y, g_y);
    cudaGetSymbolAddress((void**)&p_wqkvT, g_wqkvT);
    cudaGetSymbolAddress((void**)&p_woT, g_woT);

    // Weight transposes (tiny)
    transpose_kernel<<<(QKVDIM * NHID + 255) / 256, 256>>>(inw, p_wqkvT, QKVDIM, NHID);
    transpose_kernel<<<(NHID * NHID + 255) / 256, 256>>>(outw, p_woT, NHID, NHID);

    // x0 -> inception ; h1 ; h2
    dim3 gA(NHID / BN, N_NODES / BM);
    sgemm_nn<<<gA, 256>>>(x, ln_w, nullptr, p_inc, N_NODES, NHID, NFEAT);
    sgemm_nn<<<gA, 256>>>(x, w1, nullptr, p_h1, N_NODES, NHID, NFEAT);
    sgemm_nn<<<gA, 256>>>(x, w2, nullptr, p_h2, N_NODES, NHID, NFEAT);

    // inception += scatter(conv1) + scatter(conv2)
    int sblocks = (n_edges * 64 + 255) / 256;
    scatter_kernel<<<sblocks, 256>>>(ei1, ea1, p_h1, p_inc, n_edges);
    scatter_kernel<<<sblocks, 256>>>(ei2, ea2, p_h2, p_inc, n_edges);

    // qkv = inception @ in_proj_w^T + in_proj_b
    dim3 gQ(QKVDIM / BN, N_NODES / BM);
    sgemm_nn<<<gQ, 256>>>(p_inc, p_wqkvT, inb, p_qkv, N_NODES, QKVDIM, NHID);

    // attention -> ctx
    dim3 gAtt(NPG / 128, HEADS, NGRAPHS);
    attn_kernel<<<gAtt, 128>>>(p_qkv, p_ctx);

    // attended = ctx @ out_proj_w^T + out_proj_b
    sgemm_nn<<<gA, 256>>>(p_ctx, p_woT, outb, p_y, N_NODES, NHID, NHID);

    // out = LN(inception + attended)
    add_ln_kernel<<<N_NODES, 256>>>(p_inc, p_y, gamma, beta, out);
}

// round 3
// speedup vs baseline: 1.1354x; 1.1354x over previous
#include <cuda_runtime.h>
#include <cuda_bf16.h>
#include <math.h>

// Problem constants
#define NFEAT    128
#define NHID     256
#define HEADS    4
#define DH       64
#define N_NODES  32768
#define N_EDGES  524288
#define NGRAPHS  64
#define NPG      512            // nodes per graph
#define QKVDIM   768

typedef unsigned long long u64;

// ---------------------------------------------------------------------------
// Packed f32x2 helpers (Blackwell FFMA2 path — only reachable via PTX)
// ---------------------------------------------------------------------------
__device__ __forceinline__ void fma2(u64& d, u64 a, u64 b) {
    asm("fma.rn.f32x2 %0, %1, %2, %0;" : "+l"(d) : "l"(a), "l"(b));
}
__device__ __forceinline__ void mul2(u64& d, u64 a, u64 b) {
    asm("mul.rn.f32x2 %0, %1, %2;" : "=l"(d) : "l"(a), "l"(b));
}
__device__ __forceinline__ u64 pack_dup(float x) {
    u64 r; asm("mov.b64 %0, {%1, %1};" : "=l"(r) : "f"(x)); return r;
}
__device__ __forceinline__ u64 packf(float lo, float hi) {
    u64 r; asm("mov.b64 %0, {%1, %2};" : "=l"(r) : "f"(lo), "f"(hi)); return r;
}
__device__ __forceinline__ float2 unpack2(u64 v) {
    float2 f; asm("mov.b64 {%0, %1}, %2;" : "=f"(f.x), "=f"(f.y) : "l"(v)); return f;
}

// ---------------------------------------------------------------------------
// Scratch (static device globals; no allocation allowed)
// ---------------------------------------------------------------------------
__device__ float g_h1[N_NODES * NHID];
__device__ float g_h2[N_NODES * NHID];
__device__ float g_inc[N_NODES * NHID];        // x0, then += scatter => inception
__device__ float g_qkv[N_NODES * QKVDIM];
__device__ float g_ctx[N_NODES * NHID];
__device__ float g_y[N_NODES * NHID];          // attended (post out_proj)
__device__ float g_wqkvT[NHID * QKVDIM];       // in_proj_w^T  [256][768]
__device__ float g_woT[NHID * NHID];           // out_proj_w^T [256][256]

// ---------------------------------------------------------------------------
// Small transpose: out[c][rows] = in[r][cols]
// ---------------------------------------------------------------------------
__global__ void transpose_kernel(const float* __restrict__ in, float* __restrict__ out,
                                 int rows, int cols) {
    int idx = blockIdx.x * 256 + threadIdx.x;
    if (idx < rows * cols) {
        int r = idx / cols, c = idx % cols;
        out[c * rows + r] = in[idx];
    }
}

// ---------------------------------------------------------------------------
// SGEMM (NN) with FFMA2: C[M,N] = A[M,K] @ B[K,N] (+ bias[N])
// BM=128, BN=128, BK=16, 256 threads, 8x8 per thread (as 8x4 f32x2 pairs).
// ---------------------------------------------------------------------------
#define BM 128
#define BN 128
#define BK 16

__global__ __launch_bounds__(256) void sgemm_nn(
    const float* __restrict__ A, const float* __restrict__ B,
    const float* __restrict__ bias, float* __restrict__ C,
    int M, int N, int K)
{
    __shared__ float As[BK][BM];
    __shared__ float Bs[BK][BN];

    const int tid  = threadIdx.x;
    const int row0 = blockIdx.y * BM;
    const int col0 = blockIdx.x * BN;
    const int tm   = tid / 16;          // 0..15 -> 8 rows each
    const int tn   = tid % 16;          // 0..15 -> 8 cols each

    const int arow = tid >> 1;          // 0..127
    const int ak   = (tid & 1) * 8;     // 0 or 8
    const int brow = tid >> 4;          // 0..15
    const int bcol = (tid & 15) * 8;    // 0..120

    u64 acc2[8][4];                     // acc2[i][j] = (C[i][2j], C[i][2j+1])
    #pragma unroll
    for (int i = 0; i < 8; i++)
        #pragma unroll
        for (int j = 0; j < 4; j++) acc2[i][j] = 0ull;

    const float* Aptr = A + (size_t)(row0 + arow) * K;

    for (int k0 = 0; k0 < K; k0 += BK) {
        float4 a0 = *(const float4*)&Aptr[k0 + ak];
        float4 a1 = *(const float4*)&Aptr[k0 + ak + 4];
        As[ak + 0][arow] = a0.x; As[ak + 1][arow] = a0.y;
        As[ak + 2][arow] = a0.z; As[ak + 3][arow] = a0.w;
        As[ak + 4][arow] = a1.x; As[ak + 5][arow] = a1.y;
        As[ak + 6][arow] = a1.z; As[ak + 7][arow] = a1.w;

        const float* Bptr = B + (size_t)(k0 + brow) * N + col0 + bcol;
        *(float4*)&Bs[brow][bcol]     = *(const float4*)&Bptr[0];
        *(float4*)&Bs[brow][bcol + 4] = *(const float4*)&Bptr[4];

        __syncthreads();

        #pragma unroll
        for (int kk = 0; kk < BK; kk++) {
            float a[8];
            *(float4*)&a[0] = *(const float4*)&As[kk][tm * 8];
            *(float4*)&a[4] = *(const float4*)&As[kk][tm * 8 + 4];
            // B as packed pairs (16B-aligned reinterpret of smem)
            ulonglong2 bb0 = *(const ulonglong2*)&Bs[kk][tn * 8];
            ulonglong2 bb1 = *(const ulonglong2*)&Bs[kk][tn * 8 + 4];
            u64 b2[4] = { bb0.x, bb0.y, bb1.x, bb1.y };
            #pragma unroll
            for (int i = 0; i < 8; i++) {
                u64 ai = pack_dup(a[i]);
                #pragma unroll
                for (int j = 0; j < 4; j++)
                    fma2(acc2[i][j], ai, b2[j]);
            }
        }
        __syncthreads();
    }

    float bv[8];
    #pragma unroll
    for (int j = 0; j < 8; j++)
        bv[j] = bias ? bias[col0 + tn * 8 + j] : 0.f;

    #pragma unroll
    for (int i = 0; i < 8; i++) {
        float* cp = C + (size_t)(row0 + tm * 8 + i) * N + col0 + tn * 8;
        float2 c0 = unpack2(acc2[i][0]);
        float2 c1 = unpack2(acc2[i][1]);
        float2 c2 = unpack2(acc2[i][2]);
        float2 c3 = unpack2(acc2[i][3]);
        float4 o0 = make_float4(c0.x + bv[0], c0.y + bv[1], c1.x + bv[2], c1.y + bv[3]);
        float4 o1 = make_float4(c2.x + bv[4], c2.y + bv[5], c3.x + bv[6], c3.y + bv[7]);
        *(float4*)&cp[0] = o0;
        *(float4*)&cp[4] = o1;
    }
}

// ---------------------------------------------------------------------------
// Edge scatter: out[dst] += ea[e] * h[src]
// 64 threads/edge, one red.global.add.v4.f32 per thread (16B vector atomic).
// ---------------------------------------------------------------------------
__global__ __launch_bounds__(256) void scatter_kernel(
    const int* __restrict__ ei, const float* __restrict__ ea,
    const float* __restrict__ h, float* __restrict__ out, int n_edges)
{
    int t = blockIdx.x * 256 + threadIdx.x;
    int e = t >> 6;
    if (e >= n_edges) return;
    int lane = (t & 63) * 4;
    int src = ei[e];
    int dst = ei[n_edges + e];
    float a = ea[e];
    float4 m = *(const float4*)&h[(size_t)src * NHID + lane];
    float* o = &out[(size_t)dst * NHID + lane];
    asm volatile("red.global.add.v4.f32 [%0], {%1, %2, %3, %4};"
                 :: "l"(o), "f"(a * m.x), "f"(a * m.y), "f"(a * m.z), "f"(a * m.w)
                 : "memory");
}

// ---------------------------------------------------------------------------
// Per-graph multi-head attention (flash-style, online softmax), FFMA2 math.
// Block = (qtile 0..3, head 0..3, graph 0..63). 128 threads = 128 query rows.
// ---------------------------------------------------------------------------
__global__ __launch_bounds__(128) void attn_kernel(
    const float* __restrict__ qkv, float* __restrict__ ctx)
{
    const int qt = blockIdx.x;
    const int h  = blockIdx.y;
    const int g  = blockIdx.z;
    const int tid = threadIdx.x;

    __shared__ float Ks[64][DH];
    __shared__ float Vs[64][DH];

    const int qrow = g * NPG + qt * 128 + tid;
    const float* qp = &qkv[(size_t)qrow * QKVDIM + h * DH];

    u64 q2[32];                         // packed query pairs, pre-scaled
    #pragma unroll
    for (int i = 0; i < 16; i++) {
        float4 v = *(const float4*)&qp[i * 4];
        q2[2 * i + 0] = packf(v.x * 0.125f, v.y * 0.125f);
        q2[2 * i + 1] = packf(v.z * 0.125f, v.w * 0.125f);
    }

    float m = -1e30f, l = 0.f;
    u64 acc2[32];
    #pragma unroll
    for (int d = 0; d < 32; d++) acc2[d] = 0ull;

    for (int kt = 0; kt < NPG / 64; kt++) {
        __syncthreads();
        #pragma unroll
        for (int i = 0; i < 8; i++) {
            int idx = tid + i * 128;      // 0..1023
            int j   = idx >> 4;           // key in tile
            int dd  = (idx & 15) * 4;
            int krow = g * NPG + kt * 64 + j;
            const float* base = &qkv[(size_t)krow * QKVDIM];
            *(float4*)&Ks[j][dd] = *(const float4*)&base[NHID + h * DH + dd];
            *(float4*)&Vs[j][dd] = *(const float4*)&base[2 * NHID + h * DH + dd];
        }
        __syncthreads();

        for (int j = 0; j < 64; j++) {
            // dot(q, K[j]) with 4-way packed accumulators
            const ulonglong2* kp = (const ulonglong2*)&Ks[j][0];
            u64 s0 = 0ull, s1 = 0ull, s2 = 0ull, s3 = 0ull;
            #pragma unroll
            for (int t = 0; t < 8; t++) {
                ulonglong2 k0 = kp[2 * t];
                ulonglong2 k1 = kp[2 * t + 1];
                fma2(s0, q2[4 * t + 0], k0.x);
                fma2(s1, q2[4 * t + 1], k0.y);
                fma2(s2, q2[4 * t + 2], k1.x);
                fma2(s3, q2[4 * t + 3], k1.y);
            }
            float2 f0 = unpack2(s0), f1 = unpack2(s1);
            float2 f2 = unpack2(s2), f3 = unpack2(s3);
            float s = ((f0.x + f0.y) + (f1.x + f1.y)) + ((f2.x + f2.y) + (f3.x + f3.y));

            float p;
            if (s <= m) {
                p = __expf(s - m);
            } else {
                float scale = __expf(m - s);
                l *= scale;
                u64 sc2 = pack_dup(scale);
                #pragma unroll
                for (int d = 0; d < 32; d++) mul2(acc2[d], acc2[d], sc2);
                m = s;
                p = 1.0f;
            }
            l += p;

            u64 p2 = pack_dup(p);
            const ulonglong2* vp = (const ulonglong2*)&Vs[j][0];
            #pragma unroll
            for (int t = 0; t < 16; t++) {
                ulonglong2 vv = vp[t];
                fma2(acc2[2 * t + 0], p2, vv.x);
                fma2(acc2[2 * t + 1], p2, vv.y);
            }
        }
    }

    float inv = 1.0f / l;
    float* op = &ctx[(size_t)qrow * NHID + h * DH];
    #pragma unroll
    for (int t = 0; t < 16; t++) {
        float2 a = unpack2(acc2[2 * t + 0]);
        float2 b = unpack2(acc2[2 * t + 1]);
        float4 o = make_float4(a.x * inv, a.y * inv, b.x * inv, b.y * inv);
        *(float4*)&op[t * 4] = o;
    }
}

// ---------------------------------------------------------------------------
// out = LayerNorm(inception + attended) * gamma + beta ; one block per row
// ---------------------------------------------------------------------------
__global__ __launch_bounds__(256) void add_ln_kernel(
    const float* __restrict__ inc, const float* __restrict__ y,
    const float* __restrict__ gamma, const float* __restrict__ beta,
    float* __restrict__ out)
{
    const int row = blockIdx.x;
    const int tid = threadIdx.x;
    const size_t base = (size_t)row * NHID;

    float v = inc[base + tid] + y[base + tid];

    float s1 = v, s2 = v * v;
    #pragma unroll
    for (int o = 16; o; o >>= 1) {
        s1 += __shfl_xor_sync(0xFFFFFFFFu, s1, o);
        s2 += __shfl_xor_sync(0xFFFFFFFFu, s2, o);
    }
    __shared__ float r1[8], r2[8];
    if ((tid & 31) == 0) { r1[tid >> 5] = s1; r2[tid >> 5] = s2; }
    __syncthreads();
    float t1 = 0.f, t2 = 0.f;
    #pragma unroll
    for (int i = 0; i < 8; i++) { t1 += r1[i]; t2 += r2[i]; }

    float mu  = t1 * (1.0f / NHID);
    float var = t2 * (1.0f / NHID) - mu * mu;
    float rs  = rsqrtf(var + 1e-5f);
    out[base + tid] = (v - mu) * rs * gamma[tid] + beta[tid];
}

// ---------------------------------------------------------------------------
// Launch
// ---------------------------------------------------------------------------
extern "C" void kernel_launch(void* const* d_in, const int* in_sizes, int n_in,
                              void* d_out, int out_size)
{
    const float* x     = (const float*)d_in[0];
    const float* ea1   = (const float*)d_in[1];
    const float* ea2   = (const float*)d_in[2];
    const float* ln_w  = (const float*)d_in[3];
    const float* w1    = (const float*)d_in[4];
    const float* w2    = (const float*)d_in[5];
    const float* inw   = (const float*)d_in[6];   // [768,256]
    const float* inb   = (const float*)d_in[7];   // [768]
    const float* outw  = (const float*)d_in[8];   // [256,256]
    const float* outb  = (const float*)d_in[9];   // [256]
    const float* gamma = (const float*)d_in[10];
    const float* beta  = (const float*)d_in[11];
    const int*   ei1   = (const int*)d_in[12];
    const int*   ei2   = (const int*)d_in[13];
    float* out = (float*)d_out;

    const int n_edges = in_sizes[1];              // 524288

    float *p_h1, *p_h2, *p_inc, *p_qkv, *p_ctx, *p_y, *p_wqkvT, *p_woT;
    cudaGetSymbolAddress((void**)&p_h1, g_h1);
    cudaGetSymbolAddress((void**)&p_h2, g_h2);
    cudaGetSymbolAddress((void**)&p_inc, g_inc);
    cudaGetSymbolAddress((void**)&p_qkv, g_qkv);
    cudaGetSymbolAddress((void**)&p_ctx, g_ctx);
    cudaGetSymbolAddress((void**)&p_y, g_y);
    cudaGetSymbolAddress((void**)&p_wqkvT, g_wqkvT);
    cudaGetSymbolAddress((void**)&p_woT, g_woT);

    // Weight transposes (tiny)
    transpose_kernel<<<(QKVDIM * NHID + 255) / 256, 256>>>(inw, p_wqkvT, QKVDIM, NHID);
    transpose_kernel<<<(NHID * NHID + 255) / 256, 256>>>(outw, p_woT, NHID, NHID);

    // x0 -> inception ; h1 ; h2
    dim3 gA(NHID / BN, N_NODES / BM);
    sgemm_nn<<<gA, 256>>>(x, ln_w, nullptr, p_inc, N_NODES, NHID, NFEAT);
    sgemm_nn<<<gA, 256>>>(x, w1, nullptr, p_h1, N_NODES, NHID, NFEAT);
    sgemm_nn<<<gA, 256>>>(x, w2, nullptr, p_h2, N_NODES, NHID, NFEAT);

    // inception += scatter(conv1) + scatter(conv2)
    int sblocks = (n_edges * 64 + 255) / 256;
    scatter_kernel<<<sblocks, 256>>>(ei1, ea1, p_h1, p_inc, n_edges);
    scatter_kernel<<<sblocks, 256>>>(ei2, ea2, p_h2, p_inc, n_edges);

    // qkv = inception @ in_proj_w^T + in_proj_b
    dim3 gQ(QKVDIM / BN, N_NODES / BM);
    sgemm_nn<<<gQ, 256>>>(p_inc, p_wqkvT, inb, p_qkv, N_NODES, QKVDIM, NHID);

    // attention -> ctx
    dim3 gAtt(NPG / 128, HEADS, NGRAPHS);
    attn_kernel<<<gAtt, 128>>>(p_qkv, p_ctx);

    // attended = ctx @ out_proj_w^T + out_proj_b
    sgemm_nn<<<gA, 256>>>(p_ctx, p_woT, outb, p_y, N_NODES, NHID, NHID);

    // out = LN(inception + attended)
    add_ln_kernel<<<N_NODES, 256>>>(p_inc, p_y, gamma, beta, out);
}

// round 10
// speedup vs baseline: 1.3457x; 1.1852x over previous
#include <cuda_runtime.h>
#include <cuda_bf16.h>
#include <math.h>
#include <cstdint>

// Problem constants
#define NFEAT    128
#define NHID     256
#define HEADS    4
#define DH       64
#define N_NODES  32768
#define N_EDGES  524288
#define NGRAPHS  64
#define NPG      512
#define QKVDIM   768

typedef unsigned long long u64;

// ---------------------------------------------------------------------------
// PTX helpers (sm_80+ compatible — toolchain lowers to .target sm_103, no tcgen05)
// ---------------------------------------------------------------------------
__device__ __forceinline__ uint32_t smem_u32(const void* p) {
    uint32_t a;
    asm("{ .reg .u64 t; cvta.to.shared.u64 t, %1; cvt.u32.u64 %0, t; }" : "=r"(a) : "l"(p));
    return a;
}

#define LDSM_X4(r, a)                                                          \
    asm volatile("ldmatrix.sync.aligned.m8n8.x4.shared.b16 {%0,%1,%2,%3}, [%4];" \
        : "=r"((r)[0]), "=r"((r)[1]), "=r"((r)[2]), "=r"((r)[3]) : "r"(a))

__device__ __forceinline__ void mma16816(float* c, const uint32_t* a, const uint32_t* b) {
    asm volatile(
        "mma.sync.aligned.m16n8k16.row.col.f32.bf16.bf16.f32 "
        "{%0,%1,%2,%3}, {%4,%5,%6,%7}, {%8,%9}, {%0,%1,%2,%3};"
        : "+f"(c[0]), "+f"(c[1]), "+f"(c[2]), "+f"(c[3])
        : "r"(a[0]), "r"(a[1]), "r"(a[2]), "r"(a[3]), "r"(b[0]), "r"(b[1]));
}

#define SWZ(o) ((o) ^ (((o) >> 3) & 0x70))

// Packed f32x2 helpers (attention)
__device__ __forceinline__ void fma2(u64& d, u64 a, u64 b) {
    asm("fma.rn.f32x2 %0, %1, %2, %0;" : "+l"(d) : "l"(a), "l"(b));
}
__device__ __forceinline__ void mul2(u64& d, u64 a, u64 b) {
    asm("mul.rn.f32x2 %0, %1, %2;" : "=l"(d) : "l"(a), "l"(b));
}
__device__ __forceinline__ u64 pack_dup(float x) {
    u64 r; asm("mov.b64 %0, {%1, %1};" : "=l"(r) : "f"(x)); return r;
}
__device__ __forceinline__ u64 packf(float lo, float hi) {
    u64 r; asm("mov.b64 %0, {%1, %2};" : "=l"(r) : "f"(lo), "f"(hi)); return r;
}
__device__ __forceinline__ float2 unpack2(u64 v) {
    float2 f; asm("mov.b64 {%0, %1}, %2;" : "=f"(f.x), "=f"(f.y) : "l"(v)); return f;
}

// ---------------------------------------------------------------------------
// Scratch
// ---------------------------------------------------------------------------
__device__ float g_h1[N_NODES * NHID];
__device__ float g_h2[N_NODES * NHID];
__device__ float g_inc[N_NODES * NHID];
__device__ float g_qkv[N_NODES * QKVDIM];
__device__ float g_ctx[N_NODES * NHID];
__device__ float g_y[N_NODES * NHID];
__device__ __nv_bfloat16 g_xhi[N_NODES * NFEAT];
__device__ __nv_bfloat16 g_xlo[N_NODES * NFEAT];
__device__ __nv_bfloat16 g_ahi[N_NODES * NHID];   // inc, then ctx
__device__ __nv_bfloat16 g_alo[N_NODES * NHID];
__device__ __nv_bfloat16 g_wThi[NHID * NFEAT];    // transposed conv weight (reused x3)
__device__ __nv_bfloat16 g_wTlo[NHID * NFEAT];
__device__ __nv_bfloat16 g_wqhi[QKVDIM * NHID];
__device__ __nv_bfloat16 g_wqlo[QKVDIM * NHID];
__device__ __nv_bfloat16 g_wohi[NHID * NHID];
__device__ __nv_bfloat16 g_wolo[NHID * NHID];

// ---------------------------------------------------------------------------
// hi/lo split conversions
// ---------------------------------------------------------------------------
__global__ void cvt_hilo(const float* __restrict__ in,
                         __nv_bfloat16* __restrict__ hi, __nv_bfloat16* __restrict__ lo,
                         int n) {
    int i = blockIdx.x * 256 + threadIdx.x;
    if (i < n) {
        float x = in[i];
        __nv_bfloat16 h = __float2bfloat16(x);
        hi[i] = h;
        lo[i] = __float2bfloat16(x - __bfloat162float(h));
    }
}

// in [rows, cols] -> out [cols, rows] hi/lo
__global__ void cvt_hilo_T(const float* __restrict__ in,
                           __nv_bfloat16* __restrict__ hi, __nv_bfloat16* __restrict__ lo,
                           int rows, int cols) {
    int i = blockIdx.x * 256 + threadIdx.x;
    if (i < rows * cols) {
        int r = i / cols, c = i % cols;
        float x = in[i];
        __nv_bfloat16 h = __float2bfloat16(x);
        hi[c * rows + r] = h;
        lo[c * rows + r] = __float2bfloat16(x - __bfloat162float(h));
    }
}

// ---------------------------------------------------------------------------
// HMMA GEMM: C[M,N] = A[M,K] @ B[N,K]^T (+bias), hi/lo bf16 3-pass.
// mma.sync.m16n8k16 (.row.col, NT pattern). CTA tile 128x128, BK=64.
// 8 warps as 4(m) x 2(n); warp tile 32x64. SW128-swizzled smem (128B rows).
// ---------------------------------------------------------------------------
#define OFF_AHI 0
#define OFF_ALO 16384
#define OFF_BHI 32768
#define OFF_BLO 49152
#define SMEM_TOTAL 65536

__device__ __forceinline__ void ldtile(const __nv_bfloat16* __restrict__ src,
                                       int r0, int k0, int ld, char* dst, int tid) {
    // Full tile: 128 rows x 128 bytes = 1024 x 16B chunks, 256 threads x 4 iters
    #pragma unroll
    for (int it = 0; it < 4; it++) {
        int i  = tid + it * 256;       // 0..1023
        int r  = i >> 3;               // 0..127
        int kc = i & 7;                // 16B chunk within 128B row
        uint32_t off = SWZ((uint32_t)(r * 128 + kc * 16));
        *(uint4*)(dst + off) = *(const uint4*)(src + (size_t)(r0 + r) * ld + k0 + kc * 8);
    }
}

__global__ __launch_bounds__(256)
void hmma_gemm(const __nv_bfloat16* __restrict__ Ahi, const __nv_bfloat16* __restrict__ Alo,
               const __nv_bfloat16* __restrict__ Bhi, const __nv_bfloat16* __restrict__ Blo,
               const float* __restrict__ bias, float* __restrict__ C,
               int M, int N, int K)
{
    extern __shared__ __align__(128) char smem[];
    const uint32_t sb = smem_u32(smem);
    const int tid  = threadIdx.x;
    const int wid  = tid >> 5;
    const int lane = tid & 31;
    const int row0 = blockIdx.y * 128;
    const int col0 = blockIdx.x * 128;
    const int wm   = (wid >> 1) * 32;        // warp m offset in tile
    const int wn   = (wid & 1) * 64;         // warp n offset in tile

    float acc[2][8][4];
    #pragma unroll
    for (int mt = 0; mt < 2; mt++)
        #pragma unroll
        for (int nt = 0; nt < 8; nt++)
            #pragma unroll
            for (int j = 0; j < 4; j++) acc[mt][nt][j] = 0.f;

    // Per-lane ldmatrix address components (group g = lane>>3, r = lane&7)
    const int lg = lane >> 3;
    const int lr = lane & 7;
    // A quads: {r0-7,k0-7},{r8-15,k0-7},{r0-7,k8-15},{r8-15,k8-15}
    const int a_r  = lr + (lg & 1) * 8;
    const int a_kb = (lg >> 1) * 16;
    // B quads: {n0-7,k0-7},{n0-7,k8-15},{n8-15,k0-7},{n8-15,k8-15}
    const int b_r  = lr + (lg >> 1) * 8;
    const int b_kb = (lg & 1) * 16;

    for (int k0 = 0; k0 < K; k0 += 64) {
        ldtile(Ahi, row0, k0, K, smem + OFF_AHI, tid);
        ldtile(Alo, row0, k0, K, smem + OFF_ALO, tid);
        ldtile(Bhi, col0, k0, K, smem + OFF_BHI, tid);
        ldtile(Blo, col0, k0, K, smem + OFF_BLO, tid);
        __syncthreads();

        #pragma unroll
        for (int ks = 0; ks < 4; ks++) {
            const int kb = ks * 32;   // byte offset of this k16 step within 128B row

            uint32_t ah[2][4], al[2][4];
            #pragma unroll
            for (int mt = 0; mt < 2; mt++) {
                uint32_t off = SWZ((uint32_t)((wm + mt * 16 + a_r) * 128 + kb + a_kb));
                LDSM_X4(ah[mt], sb + OFF_AHI + off);
                LDSM_X4(al[mt], sb + OFF_ALO + off);
            }
            uint32_t bh[4][4], bl[4][4];
            #pragma unroll
            for (int p = 0; p < 4; p++) {
                uint32_t off = SWZ((uint32_t)((wn + p * 16 + b_r) * 128 + kb + b_kb));
                LDSM_X4(bh[p], sb + OFF_BHI + off);
                LDSM_X4(bl[p], sb + OFF_BLO + off);
            }
            #pragma unroll
            for (int mt = 0; mt < 2; mt++)
                #pragma unroll
                for (int nt = 0; nt < 8; nt++) {
                    const uint32_t* Bh = &bh[nt >> 1][(nt & 1) * 2];
                    const uint32_t* Bl = &bl[nt >> 1][(nt & 1) * 2];
                    mma16816(acc[mt][nt], ah[mt], Bh);   // hi*hi
                    mma16816(acc[mt][nt], ah[mt], Bl);   // hi*lo
                    mma16816(acc[mt][nt], al[mt], Bh);   // lo*hi
                }
        }
        __syncthreads();
    }

    // Epilogue: direct fp32 stores (float2 per fragment half-row)
    const int cbase = col0 + wn + (lane & 3) * 2;
    const int rbase = row0 + wm + (lane >> 2);
    #pragma unroll
    for (int nt = 0; nt < 8; nt++) {
        float b0 = 0.f, b1 = 0.f;
        if (bias) { b0 = bias[cbase + nt * 8]; b1 = bias[cbase + nt * 8 + 1]; }
        #pragma unroll
        for (int mt = 0; mt < 2; mt++) {
            float* p0 = C + (size_t)(rbase + mt * 16) * N + cbase + nt * 8;
            float* p1 = C + (size_t)(rbase + mt * 16 + 8) * N + cbase + nt * 8;
            *(float2*)p0 = make_float2(acc[mt][nt][0] + b0, acc[mt][nt][1] + b1);
            *(float2*)p1 = make_float2(acc[mt][nt][2] + b0, acc[mt][nt][3] + b1);
        }
    }
}

// ---------------------------------------------------------------------------
// Edge scatter: out[dst] += ea[e] * h[src]  (64 thr/edge, red.v4)
// ---------------------------------------------------------------------------
__global__ __launch_bounds__(256) void scatter_kernel(
    const int* __restrict__ ei, const float* __restrict__ ea,
    const float* __restrict__ h, float* __restrict__ out, int n_edges)
{
    int t = blockIdx.x * 256 + threadIdx.x;
    int e = t >> 6;
    if (e >= n_edges) return;
    int lane = (t & 63) * 4;
    int src = ei[e];
    int dst = ei[n_edges + e];
    float a = ea[e];
    float4 m = *(const float4*)&h[(size_t)src * NHID + lane];
    float* o = &out[(size_t)dst * NHID + lane];
    asm volatile("red.global.add.v4.f32 [%0], {%1, %2, %3, %4};"
                 :: "l"(o), "f"(a * m.x), "f"(a * m.y), "f"(a * m.z), "f"(a * m.w)
                 : "memory");
}

// ---------------------------------------------------------------------------
// Per-graph MHA (flash-style, online softmax), f32x2 math
// ---------------------------------------------------------------------------
__global__ __launch_bounds__(128) void attn_kernel(
    const float* __restrict__ qkv, float* __restrict__ ctx)
{
    const int qt = blockIdx.x;
    const int h  = blockIdx.y;
    const int g  = blockIdx.z;
    const int tid = threadIdx.x;

    __shared__ float Ks[64][DH];
    __shared__ float Vs[64][DH];

    const int qrow = g * NPG + qt * 128 + tid;
    const float* qp = &qkv[(size_t)qrow * QKVDIM + h * DH];

    u64 q2[32];
    #pragma unroll
    for (int i = 0; i < 16; i++) {
        float4 v = *(const float4*)&qp[i * 4];
        q2[2 * i + 0] = packf(v.x * 0.125f, v.y * 0.125f);
        q2[2 * i + 1] = packf(v.z * 0.125f, v.w * 0.125f);
    }

    float m = -1e30f, l = 0.f;
    u64 acc2[32];
    #pragma unroll
    for (int d = 0; d < 32; d++) acc2[d] = 0ull;

    for (int kt = 0; kt < NPG / 64; kt++) {
        __syncthreads();
        #pragma unroll
        for (int i = 0; i < 8; i++) {
            int idx = tid + i * 128;
            int j   = idx >> 4;
            int dd  = (idx & 15) * 4;
            int krow = g * NPG + kt * 64 + j;
            const float* base = &qkv[(size_t)krow * QKVDIM];
            *(float4*)&Ks[j][dd] = *(const float4*)&base[NHID + h * DH + dd];
            *(float4*)&Vs[j][dd] = *(const float4*)&base[2 * NHID + h * DH + dd];
        }
        __syncthreads();

        for (int j = 0; j < 64; j++) {
            const ulonglong2* kp = (const ulonglong2*)&Ks[j][0];
            u64 s0 = 0ull, s1 = 0ull, s2 = 0ull, s3 = 0ull;
            #pragma unroll
            for (int t = 0; t < 8; t++) {
                ulonglong2 k0 = kp[2 * t];
                ulonglong2 k1 = kp[2 * t + 1];
                fma2(s0, q2[4 * t + 0], k0.x);
                fma2(s1, q2[4 * t + 1], k0.y);
                fma2(s2, q2[4 * t + 2], k1.x);
                fma2(s3, q2[4 * t + 3], k1.y);
            }
            float2 f0 = unpack2(s0), f1 = unpack2(s1);
            float2 f2 = unpack2(s2), f3 = unpack2(s3);
            float s = ((f0.x + f0.y) + (f1.x + f1.y)) + ((f2.x + f2.y) + (f3.x + f3.y));

            float p;
            if (s <= m) {
                p = __expf(s - m);
            } else {
                float scale = __expf(m - s);
                l *= scale;
                u64 sc2 = pack_dup(scale);
                #pragma unroll
                for (int d = 0; d < 32; d++) mul2(acc2[d], acc2[d], sc2);
                m = s;
                p = 1.0f;
            }
            l += p;

            u64 p2 = pack_dup(p);
            const ulonglong2* vp = (const ulonglong2*)&Vs[j][0];
            #pragma unroll
            for (int t = 0; t < 16; t++) {
                ulonglong2 vv = vp[t];
                fma2(acc2[2 * t + 0], p2, vv.x);
                fma2(acc2[2 * t + 1], p2, vv.y);
            }
        }
    }

    float inv = 1.0f / l;
    float* op = &ctx[(size_t)qrow * NHID + h * DH];
    #pragma unroll
    for (int t = 0; t < 16; t++) {
        float2 a = unpack2(acc2[2 * t + 0]);
        float2 b = unpack2(acc2[2 * t + 1]);
        float4 o = make_float4(a.x * inv, a.y * inv, b.x * inv, b.y * inv);
        *(float4*)&op[t * 4] = o;
    }
}

// ---------------------------------------------------------------------------
// out = LayerNorm(inception + attended)
// ---------------------------------------------------------------------------
__global__ __launch_bounds__(256) void add_ln_kernel(
    const float* __restrict__ inc, const float* __restrict__ y,
    const float* __restrict__ gamma, const float* __restrict__ beta,
    float* __restrict__ out)
{
    const int row = blockIdx.x;
    const int tid = threadIdx.x;
    const size_t base = (size_t)row * NHID;

    float v = inc[base + tid] + y[base + tid];

    float s1 = v, s2 = v * v;
    #pragma unroll
    for (int o = 16; o; o >>= 1) {
        s1 += __shfl_xor_sync(0xFFFFFFFFu, s1, o);
        s2 += __shfl_xor_sync(0xFFFFFFFFu, s2, o);
    }
    __shared__ float r1[8], r2[8];
    if ((tid & 31) == 0) { r1[tid >> 5] = s1; r2[tid >> 5] = s2; }
    __syncthreads();
    float t1 = 0.f, t2 = 0.f;
    #pragma unroll
    for (int i = 0; i < 8; i++) { t1 += r1[i]; t2 += r2[i]; }

    float mu  = t1 * (1.0f / NHID);
    float var = t2 * (1.0f / NHID) - mu * mu;
    float rs  = rsqrtf(var + 1e-5f);
    out[base + tid] = (v - mu) * rs * gamma[tid] + beta[tid];
}

// ---------------------------------------------------------------------------
// Launch
// ---------------------------------------------------------------------------
extern "C" void kernel_launch(void* const* d_in, const int* in_sizes, int n_in,
                              void* d_out, int out_size)
{
    const float* x     = (const float*)d_in[0];
    const float* ea1   = (const float*)d_in[1];
    const float* ea2   = (const float*)d_in[2];
    const float* ln_w  = (const float*)d_in[3];
    const float* w1    = (const float*)d_in[4];
    const float* w2    = (const float*)d_in[5];
    const float* inw   = (const float*)d_in[6];   // [768,256] = [N,K]
    const float* inb   = (const float*)d_in[7];
    const float* outw  = (const float*)d_in[8];   // [256,256] = [N,K]
    const float* outb  = (const float*)d_in[9];
    const float* gamma = (const float*)d_in[10];
    const float* beta  = (const float*)d_in[11];
    const int*   ei1   = (const int*)d_in[12];
    const int*   ei2   = (const int*)d_in[13];
    float* out = (float*)d_out;

    const int n_edges = in_sizes[1];

    float *p_h1, *p_h2, *p_inc, *p_qkv, *p_ctx, *p_y;
    __nv_bfloat16 *p_xhi, *p_xlo, *p_ahi, *p_alo, *p_wThi, *p_wTlo;
    __nv_bfloat16 *p_wqhi, *p_wqlo, *p_wohi, *p_wolo;
    cudaGetSymbolAddress((void**)&p_h1, g_h1);
    cudaGetSymbolAddress((void**)&p_h2, g_h2);
    cudaGetSymbolAddress((void**)&p_inc, g_inc);
    cudaGetSymbolAddress((void**)&p_qkv, g_qkv);
    cudaGetSymbolAddress((void**)&p_ctx, g_ctx);
    cudaGetSymbolAddress((void**)&p_y, g_y);
    cudaGetSymbolAddress((void**)&p_xhi, g_xhi);
    cudaGetSymbolAddress((void**)&p_xlo, g_xlo);
    cudaGetSymbolAddress((void**)&p_ahi, g_ahi);
    cudaGetSymbolAddress((void**)&p_alo, g_alo);
    cudaGetSymbolAddress((void**)&p_wThi, g_wThi);
    cudaGetSymbolAddress((void**)&p_wTlo, g_wTlo);
    cudaGetSymbolAddress((void**)&p_wqhi, g_wqhi);
    cudaGetSymbolAddress((void**)&p_wqlo, g_wqlo);
    cudaGetSymbolAddress((void**)&p_wohi, g_wohi);
    cudaGetSymbolAddress((void**)&p_wolo, g_wolo);

    cudaFuncSetAttribute(hmma_gemm, cudaFuncAttributeMaxDynamicSharedMemorySize, SMEM_TOTAL);

    // x -> hi/lo
    cvt_hilo<<<(N_NODES * NFEAT + 255) / 256, 256>>>(x, p_xhi, p_xlo, N_NODES * NFEAT);

    // x0 = x @ ln_w ; h1 = x @ conv1_w ; h2 = x @ conv2_w  (weights [128,256] -> [256,128])
    dim3 gA(NHID / 128, N_NODES / 128);
    cvt_hilo_T<<<(NFEAT * NHID + 255) / 256, 256>>>(ln_w, p_wThi, p_wTlo, NFEAT, NHID);
    hmma_gemm<<<gA, 256, SMEM_TOTAL>>>(p_xhi, p_xlo, p_wThi, p_wTlo, nullptr, p_inc,
                                       N_NODES, NHID, NFEAT);
    cvt_hilo_T<<<(NFEAT * NHID + 255) / 256, 256>>>(w1, p_wThi, p_wTlo, NFEAT, NHID);
    hmma_gemm<<<gA, 256, SMEM_TOTAL>>>(p_xhi, p_xlo, p_wThi, p_wTlo, nullptr, p_h1,
                                       N_NODES, NHID, NFEAT);
    cvt_hilo_T<<<(NFEAT * NHID + 255) / 256, 256>>>(w2, p_wThi, p_wTlo, NFEAT, NHID);
    hmma_gemm<<<gA, 256, SMEM_TOTAL>>>(p_xhi, p_xlo, p_wThi, p_wTlo, nullptr, p_h2,
                                       N_NODES, NHID, NFEAT);

    // scatter into inception
    int sblocks = (n_edges * 64 + 255) / 256;
    scatter_kernel<<<sblocks, 256>>>(ei1, ea1, p_h1, p_inc, n_edges);
    scatter_kernel<<<sblocks, 256>>>(ei2, ea2, p_h2, p_inc, n_edges);

    // qkv = inc @ in_proj_w^T + b     (in_proj_w already [N=768, K=256])
    cvt_hilo<<<(N_NODES * NHID + 255) / 256, 256>>>(p_inc, p_ahi, p_alo, N_NODES * NHID);
    cvt_hilo<<<(QKVDIM * NHID + 255) / 256, 256>>>(inw, p_wqhi, p_wqlo, QKVDIM * NHID);
    dim3 gQ(QKVDIM / 128, N_NODES / 128);
    hmma_gemm<<<gQ, 256, SMEM_TOTAL>>>(p_ahi, p_alo, p_wqhi, p_wqlo, inb, p_qkv,
                                       N_NODES, QKVDIM, NHID);

    // attention
    dim3 gAtt(NPG / 128, HEADS, NGRAPHS);
    attn_kernel<<<gAtt, 128>>>(p_qkv, p_ctx);

    // y = ctx @ out_proj_w^T + b      (out_proj_w already [N=256, K=256])
    cvt_hilo<<<(N_NODES * NHID + 255) / 256, 256>>>(p_ctx, p_ahi, p_alo, N_NODES * NHID);
    cvt_hilo<<<(NHID * NHID + 255) / 256, 256>>>(outw, p_wohi, p_wolo, NHID * NHID);
    hmma_gemm<<<gA, 256, SMEM_TOTAL>>>(p_ahi, p_alo, p_wohi, p_wolo, outb, p_y,
                                       N_NODES, NHID, NHID);

    // out = LN(inc + y)
    add_ln_kernel<<<N_NODES, 256>>>(p_inc, p_y, gamma, beta, out);
}

// round 11
// speedup vs baseline: 2.3845x; 1.7720x over previous
#include <cuda_runtime.h>
#include <cuda_bf16.h>
#include <math.h>
#include <cstdint>

// Problem constants
#define NFEAT    128
#define NHID     256
#define HEADS    4
#define DH       64
#define N_NODES  32768
#define N_EDGES  524288
#define NGRAPHS  64
#define NPG      512
#define QKVDIM   768

typedef unsigned long long u64;

// ---------------------------------------------------------------------------
// PTX helpers (sm_80+ compatible — toolchain lowers to .target sm_103, no tcgen05)
// ---------------------------------------------------------------------------
__device__ __forceinline__ uint32_t smem_u32(const void* p) {
    uint32_t a;
    asm("{ .reg .u64 t; cvta.to.shared.u64 t, %1; cvt.u32.u64 %0, t; }" : "=r"(a) : "l"(p));
    return a;
}

#define LDSM_X4(r, a)                                                          \
    asm volatile("ldmatrix.sync.aligned.m8n8.x4.shared.b16 {%0,%1,%2,%3}, [%4];" \
        : "=r"((r)[0]), "=r"((r)[1]), "=r"((r)[2]), "=r"((r)[3]) : "r"(a))

#define LDSM_X4_T(r, a)                                                        \
    asm volatile("ldmatrix.sync.aligned.m8n8.x4.trans.shared.b16 {%0,%1,%2,%3}, [%4];" \
        : "=r"((r)[0]), "=r"((r)[1]), "=r"((r)[2]), "=r"((r)[3]) : "r"(a))

__device__ __forceinline__ void mma16816(float* c, const uint32_t* a, const uint32_t* b) {
    asm volatile(
        "mma.sync.aligned.m16n8k16.row.col.f32.bf16.bf16.f32 "
        "{%0,%1,%2,%3}, {%4,%5,%6,%7}, {%8,%9}, {%0,%1,%2,%3};"
        : "+f"(c[0]), "+f"(c[1]), "+f"(c[2]), "+f"(c[3])
        : "r"(a[0]), "r"(a[1]), "r"(a[2]), "r"(a[3]), "r"(b[0]), "r"(b[1]));
}

#define SWZ(o) ((o) ^ (((o) >> 3) & 0x70))

// pack (lo, hi) floats -> bf16x2 register (lo in low 16 bits)
__device__ __forceinline__ uint32_t packbf(float lo, float hi) {
    uint32_t r;
    asm("cvt.rn.bf16x2.f32 %0, %1, %2;" : "=r"(r) : "f"(hi), "f"(lo));
    return r;
}
__device__ __forceinline__ float bfres(float x) {
    __nv_bfloat16 h = __float2bfloat16(x);
    return x - __bfloat162float(h);
}

// ---------------------------------------------------------------------------
// Scratch
// ---------------------------------------------------------------------------
__device__ float g_h1[N_NODES * NHID];
__device__ float g_h2[N_NODES * NHID];
__device__ float g_inc[N_NODES * NHID];
__device__ float g_y[N_NODES * NHID];
__device__ __nv_bfloat16 g_xhi[N_NODES * NFEAT];
__device__ __nv_bfloat16 g_xlo[N_NODES * NFEAT];
__device__ __nv_bfloat16 g_ahi[N_NODES * NHID];    // inc hi, then ctx hi
__device__ __nv_bfloat16 g_alo[N_NODES * NHID];
__device__ __nv_bfloat16 g_qkvh[N_NODES * QKVDIM];
__device__ __nv_bfloat16 g_qkvl[N_NODES * QKVDIM];
__device__ __nv_bfloat16 g_wThi[NHID * NFEAT];
__device__ __nv_bfloat16 g_wTlo[NHID * NFEAT];
__device__ __nv_bfloat16 g_wqhi[QKVDIM * NHID];
__device__ __nv_bfloat16 g_wqlo[QKVDIM * NHID];
__device__ __nv_bfloat16 g_wohi[NHID * NHID];
__device__ __nv_bfloat16 g_wolo[NHID * NHID];

// ---------------------------------------------------------------------------
// hi/lo split conversions
// ---------------------------------------------------------------------------
__global__ void cvt_hilo(const float* __restrict__ in,
                         __nv_bfloat16* __restrict__ hi, __nv_bfloat16* __restrict__ lo,
                         int n) {
    int i = blockIdx.x * 256 + threadIdx.x;
    if (i < n) {
        float x = in[i];
        __nv_bfloat16 h = __float2bfloat16(x);
        hi[i] = h;
        lo[i] = __float2bfloat16(x - __bfloat162float(h));
    }
}

__global__ void cvt_hilo_T(const float* __restrict__ in,
                           __nv_bfloat16* __restrict__ hi, __nv_bfloat16* __restrict__ lo,
                           int rows, int cols) {
    int i = blockIdx.x * 256 + threadIdx.x;
    if (i < rows * cols) {
        int r = i / cols, c = i % cols;
        float x = in[i];
        __nv_bfloat16 h = __float2bfloat16(x);
        hi[c * rows + r] = h;
        lo[c * rows + r] = __float2bfloat16(x - __bfloat162float(h));
    }
}

// ---------------------------------------------------------------------------
// HMMA GEMM: C[M,N] = A[M,K] @ B[N,K]^T (+bias), hi/lo bf16 3-pass.
// CTA tile 128x128, BK=64, 8 warps (4m x 2n), warp tile 32x64.
// Output either fp32 (Cf) or bf16 hi/lo (Chi/Clo).
// ---------------------------------------------------------------------------
#define OFF_AHI 0
#define OFF_ALO 16384
#define OFF_BHI 32768
#define OFF_BLO 49152
#define SMEM_TOTAL 65536

__device__ __forceinline__ void ldtile(const __nv_bfloat16* __restrict__ src,
                                       int r0, int k0, int ld, char* dst, int tid) {
    #pragma unroll
    for (int it = 0; it < 4; it++) {
        int i  = tid + it * 256;       // 0..1023
        int r  = i >> 3;               // 0..127
        int kc = i & 7;                // 16B chunk within 128B row
        uint32_t off = SWZ((uint32_t)(r * 128 + kc * 16));
        *(uint4*)(dst + off) = *(const uint4*)(src + (size_t)(r0 + r) * ld + k0 + kc * 8);
    }
}

__global__ __launch_bounds__(256)
void hmma_gemm(const __nv_bfloat16* __restrict__ Ahi, const __nv_bfloat16* __restrict__ Alo,
               const __nv_bfloat16* __restrict__ Bhi, const __nv_bfloat16* __restrict__ Blo,
               const float* __restrict__ bias,
               float* __restrict__ Cf,
               __nv_bfloat16* __restrict__ Chi, __nv_bfloat16* __restrict__ Clo,
               int M, int N, int K)
{
    extern __shared__ __align__(128) char smem[];
    const uint32_t sb = smem_u32(smem);
    const int tid  = threadIdx.x;
    const int wid  = tid >> 5;
    const int lane = tid & 31;
    const int row0 = blockIdx.y * 128;
    const int col0 = blockIdx.x * 128;
    const int wm   = (wid >> 1) * 32;
    const int wn   = (wid & 1) * 64;

    float acc[2][8][4];
    #pragma unroll
    for (int mt = 0; mt < 2; mt++)
        #pragma unroll
        for (int nt = 0; nt < 8; nt++)
            #pragma unroll
            for (int j = 0; j < 4; j++) acc[mt][nt][j] = 0.f;

    const int lg = lane >> 3;
    const int lr = lane & 7;
    const int a_r  = lr + (lg & 1) * 8;
    const int a_kb = (lg >> 1) * 16;
    const int b_r  = lr + (lg >> 1) * 8;
    const int b_kb = (lg & 1) * 16;

    for (int k0 = 0; k0 < K; k0 += 64) {
        ldtile(Ahi, row0, k0, K, smem + OFF_AHI, tid);
        ldtile(Alo, row0, k0, K, smem + OFF_ALO, tid);
        ldtile(Bhi, col0, k0, K, smem + OFF_BHI, tid);
        ldtile(Blo, col0, k0, K, smem + OFF_BLO, tid);
        __syncthreads();

        #pragma unroll
        for (int ks = 0; ks < 4; ks++) {
            const int kb = ks * 32;

            uint32_t ah[2][4], al[2][4];
            #pragma unroll
            for (int mt = 0; mt < 2; mt++) {
                uint32_t off = SWZ((uint32_t)((wm + mt * 16 + a_r) * 128 + kb + a_kb));
                LDSM_X4(ah[mt], sb + OFF_AHI + off);
                LDSM_X4(al[mt], sb + OFF_ALO + off);
            }
            uint32_t bh[4][4], bl[4][4];
            #pragma unroll
            for (int p = 0; p < 4; p++) {
                uint32_t off = SWZ((uint32_t)((wn + p * 16 + b_r) * 128 + kb + b_kb));
                LDSM_X4(bh[p], sb + OFF_BHI + off);
                LDSM_X4(bl[p], sb + OFF_BLO + off);
            }
            #pragma unroll
            for (int mt = 0; mt < 2; mt++)
                #pragma unroll
                for (int nt = 0; nt < 8; nt++) {
                    const uint32_t* Bh = &bh[nt >> 1][(nt & 1) * 2];
                    const uint32_t* Bl = &bl[nt >> 1][(nt & 1) * 2];
                    mma16816(acc[mt][nt], ah[mt], Bh);
                    mma16816(acc[mt][nt], ah[mt], Bl);
                    mma16816(acc[mt][nt], al[mt], Bh);
                }
        }
        __syncthreads();
    }

    const int cbase = col0 + wn + (lane & 3) * 2;
    const int rbase = row0 + wm + (lane >> 2);
    #pragma unroll
    for (int nt = 0; nt < 8; nt++) {
        float b0 = 0.f, b1 = 0.f;
        if (bias) { b0 = bias[cbase + nt * 8]; b1 = bias[cbase + nt * 8 + 1]; }
        #pragma unroll
        for (int mt = 0; mt < 2; mt++) {
            int r0 = rbase + mt * 16;
            float v00 = acc[mt][nt][0] + b0, v01 = acc[mt][nt][1] + b1;   // row r0
            float v10 = acc[mt][nt][2] + b0, v11 = acc[mt][nt][3] + b1;   // row r0+8
            if (Cf) {
                *(float2*)(Cf + (size_t)r0 * N + cbase + nt * 8)       = make_float2(v00, v01);
                *(float2*)(Cf + (size_t)(r0 + 8) * N + cbase + nt * 8) = make_float2(v10, v11);
            } else {
                size_t i0 = (size_t)r0 * N + cbase + nt * 8;
                size_t i1 = (size_t)(r0 + 8) * N + cbase + nt * 8;
                *(uint32_t*)(Chi + i0) = packbf(v00, v01);
                *(uint32_t*)(Chi + i1) = packbf(v10, v11);
                *(uint32_t*)(Clo + i0) = packbf(bfres(v00), bfres(v01));
                *(uint32_t*)(Clo + i1) = packbf(bfres(v10), bfres(v11));
            }
        }
    }
}

// ---------------------------------------------------------------------------
// Edge scatter: out[dst] += ea[e] * h[src]  (64 thr/edge, red.v4)
// ---------------------------------------------------------------------------
__global__ __launch_bounds__(256) void scatter_kernel(
    const int* __restrict__ ei, const float* __restrict__ ea,
    const float* __restrict__ h, float* __restrict__ out, int n_edges)
{
    int t = blockIdx.x * 256 + threadIdx.x;
    int e = t >> 6;
    if (e >= n_edges) return;
    int lane = (t & 63) * 4;
    int src = ei[e];
    int dst = ei[n_edges + e];
    float a = ea[e];
    float4 m = *(const float4*)&h[(size_t)src * NHID + lane];
    float* o = &out[(size_t)dst * NHID + lane];
    asm volatile("red.global.add.v4.f32 [%0], {%1, %2, %3, %4};"
                 :: "l"(o), "f"(a * m.x), "f"(a * m.y), "f"(a * m.z), "f"(a * m.w)
                 : "memory");
}

// ---------------------------------------------------------------------------
// Flash attention with mma.sync (FA2 register layout), hi/lo bf16 3-pass.
// CTA = (qtile of 128, head, graph), 4 warps, warp = 32 q rows.
// Reads qkv hi/lo bf16; writes ctx hi/lo bf16.
// ---------------------------------------------------------------------------
__global__ __launch_bounds__(128)
void attn_mma(const __nv_bfloat16* __restrict__ Qh, const __nv_bfloat16* __restrict__ Ql,
              __nv_bfloat16* __restrict__ Ch, __nv_bfloat16* __restrict__ Cl)
{
    __shared__ __align__(128) char sm[32768];
    char* Khp = sm;          char* Klp = sm + 8192;
    char* Vhp = sm + 16384;  char* Vlp = sm + 24576;
    const uint32_t sKh = smem_u32(Khp), sKl = smem_u32(Klp);
    const uint32_t sVh = smem_u32(Vhp), sVl = smem_u32(Vlp);

    const int qt = blockIdx.x, h = blockIdx.y, g = blockIdx.z;
    const int tid = threadIdx.x, wid = tid >> 5, lane = tid & 31;
    const int wm = wid * 32;
    const int node0 = g * NPG;
    const int q0 = node0 + qt * 128;
    const int qcol = h * DH;
    const int kcol = NHID + h * DH;
    const int vcol = 2 * NHID + h * DH;

    const int rl = lane >> 2;          // fragment row within 8
    const int kp = (lane & 3) * 2;     // fragment col pair

    // Q fragments (A operand, resident)
    uint32_t qfh[2][4][4], qfl[2][4][4];
    #pragma unroll
    for (int mt = 0; mt < 2; mt++)
        #pragma unroll
        for (int ks = 0; ks < 4; ks++) {
            size_t base = (size_t)(q0 + wm + mt * 16 + rl) * QKVDIM + qcol + ks * 16 + kp;
            qfh[mt][ks][0] = *(const uint32_t*)(Qh + base);
            qfh[mt][ks][1] = *(const uint32_t*)(Qh + base + 8 * QKVDIM);
            qfh[mt][ks][2] = *(const uint32_t*)(Qh + base + 8);
            qfh[mt][ks][3] = *(const uint32_t*)(Qh + base + 8 * QKVDIM + 8);
            qfl[mt][ks][0] = *(const uint32_t*)(Ql + base);
            qfl[mt][ks][1] = *(const uint32_t*)(Ql + base + 8 * QKVDIM);
            qfl[mt][ks][2] = *(const uint32_t*)(Ql + base + 8);
            qfl[mt][ks][3] = *(const uint32_t*)(Ql + base + 8 * QKVDIM + 8);
        }

    float o[2][8][4];
    #pragma unroll
    for (int mt = 0; mt < 2; mt++)
        #pragma unroll
        for (int nt = 0; nt < 8; nt++)
            #pragma unroll
            for (int j = 0; j < 4; j++) o[mt][nt][j] = 0.f;
    float mst[2][2] = {{-1e30f, -1e30f}, {-1e30f, -1e30f}};
    float lst[2][2] = {{0.f, 0.f}, {0.f, 0.f}};

    // B-frag lane addressing (non-trans, for K)
    const int lg = lane >> 3, lr = lane & 7;
    const int b_r  = lr + (lg >> 1) * 8;
    const int b_kb = (lg & 1) * 16;
    // trans addressing (for V)
    const int v_r  = lane & 15;
    const int v_cb = (lane >> 4) * 16;

    for (int kt = 0; kt < NPG / 64; kt++) {
        __syncthreads();
        #pragma unroll
        for (int it = 0; it < 4; it++) {
            int i = tid + it * 128;        // 0..511
            int row = i >> 3, c = i & 7;
            size_t gidx = (size_t)(node0 + kt * 64 + row) * QKVDIM;
            uint32_t off = SWZ((uint32_t)(row * 128 + c * 16));
            *(uint4*)(Khp + off) = *(const uint4*)(Qh + gidx + kcol + c * 8);
            *(uint4*)(Klp + off) = *(const uint4*)(Ql + gidx + kcol + c * 8);
            *(uint4*)(Vhp + off) = *(const uint4*)(Qh + gidx + vcol + c * 8);
            *(uint4*)(Vlp + off) = *(const uint4*)(Ql + gidx + vcol + c * 8);
        }
        __syncthreads();

        // S = Q K^T (3-pass hi/lo)
        float s[2][8][4];
        #pragma unroll
        for (int mt = 0; mt < 2; mt++)
            #pragma unroll
            for (int nt = 0; nt < 8; nt++)
                #pragma unroll
                for (int j = 0; j < 4; j++) s[mt][nt][j] = 0.f;

        #pragma unroll
        for (int ks = 0; ks < 4; ks++) {
            uint32_t bh[4][4], bl[4][4];
            #pragma unroll
            for (int p = 0; p < 4; p++) {
                uint32_t off = SWZ((uint32_t)((p * 16 + b_r) * 128 + ks * 32 + b_kb));
                LDSM_X4(bh[p], sKh + off);
                LDSM_X4(bl[p], sKl + off);
            }
            #pragma unroll
            for (int mt = 0; mt < 2; mt++)
                #pragma unroll
                for (int nt = 0; nt < 8; nt++) {
                    const uint32_t* Bh = &bh[nt >> 1][(nt & 1) * 2];
                    const uint32_t* Bl = &bl[nt >> 1][(nt & 1) * 2];
                    mma16816(s[mt][nt], qfh[mt][ks], Bh);
                    mma16816(s[mt][nt], qfh[mt][ks], Bl);
                    mma16816(s[mt][nt], qfl[mt][ks], Bh);
                }
        }

        // Online softmax (scale 1/8 folded into exp argument)
        #pragma unroll
        for (int mt = 0; mt < 2; mt++)
            #pragma unroll
            for (int rh = 0; rh < 2; rh++) {
                const int i0 = rh * 2;
                float vmax = -1e30f;
                #pragma unroll
                for (int nt = 0; nt < 8; nt++)
                    vmax = fmaxf(vmax, fmaxf(s[mt][nt][i0], s[mt][nt][i0 + 1]));
                vmax = fmaxf(vmax, __shfl_xor_sync(0xFFFFFFFFu, vmax, 1));
                vmax = fmaxf(vmax, __shfl_xor_sync(0xFFFFFFFFu, vmax, 2));
                float mo = mst[mt][rh];
                float mn = fmaxf(mo, vmax);
                float sc = __expf((mo - mn) * 0.125f);
                float sum = 0.f;
                #pragma unroll
                for (int nt = 0; nt < 8; nt++) {
                    float p0 = __expf((s[mt][nt][i0]     - mn) * 0.125f);
                    float p1 = __expf((s[mt][nt][i0 + 1] - mn) * 0.125f);
                    s[mt][nt][i0] = p0; s[mt][nt][i0 + 1] = p1;
                    sum += p0 + p1;
                }
                sum += __shfl_xor_sync(0xFFFFFFFFu, sum, 1);
                sum += __shfl_xor_sync(0xFFFFFFFFu, sum, 2);
                lst[mt][rh] = lst[mt][rh] * sc + sum;
                mst[mt][rh] = mn;
                #pragma unroll
                for (int nt = 0; nt < 8; nt++) {
                    o[mt][nt][i0] *= sc;
                    o[mt][nt][i0 + 1] *= sc;
                }
            }

        // O += P V (P packed in-register C->A layout; 3-pass hi/lo)
        #pragma unroll
        for (int ks = 0; ks < 4; ks++) {
            uint32_t vh[4][4], vl[4][4];
            #pragma unroll
            for (int d4 = 0; d4 < 4; d4++) {
                uint32_t off = SWZ((uint32_t)((ks * 16 + v_r) * 128 + d4 * 32 + v_cb));
                LDSM_X4_T(vh[d4], sVh + off);
                LDSM_X4_T(vl[d4], sVl + off);
            }
            #pragma unroll
            for (int mt = 0; mt < 2; mt++) {
                float a0 = s[mt][2 * ks][0],     a1 = s[mt][2 * ks][1];
                float a2 = s[mt][2 * ks][2],     a3 = s[mt][2 * ks][3];
                float c0 = s[mt][2 * ks + 1][0], c1 = s[mt][2 * ks + 1][1];
                float c2 = s[mt][2 * ks + 1][2], c3 = s[mt][2 * ks + 1][3];
                uint32_t pah[4], pal[4];
                pah[0] = packbf(a0, a1); pah[1] = packbf(a2, a3);
                pah[2] = packbf(c0, c1); pah[3] = packbf(c2, c3);
                pal[0] = packbf(bfres(a0), bfres(a1)); pal[1] = packbf(bfres(a2), bfres(a3));
                pal[2] = packbf(bfres(c0), bfres(c1)); pal[3] = packbf(bfres(c2), bfres(c3));
                #pragma unroll
                for (int nt = 0; nt < 8; nt++) {
                    const uint32_t* Bh = &vh[nt >> 1][(nt & 1) * 2];
                    const uint32_t* Bl = &vl[nt >> 1][(nt & 1) * 2];
                    mma16816(o[mt][nt], pah, Bh);
                    mma16816(o[mt][nt], pah, Bl);
                    mma16816(o[mt][nt], pal, Bh);
                }
            }
        }
    }

    // Epilogue: ctx = O / l, written as bf16 hi/lo
    #pragma unroll
    for (int mt = 0; mt < 2; mt++)
        #pragma unroll
        for (int rh = 0; rh < 2; rh++) {
            float inv = 1.0f / lst[mt][rh];
            int row = q0 + wm + mt * 16 + rh * 8 + rl;
            #pragma unroll
            for (int nt = 0; nt < 8; nt++) {
                float v0 = o[mt][nt][rh * 2]     * inv;
                float v1 = o[mt][nt][rh * 2 + 1] * inv;
                size_t idx = (size_t)row * NHID + qcol + nt * 8 + kp;
                *(uint32_t*)(Ch + idx) = packbf(v0, v1);
                *(uint32_t*)(Cl + idx) = packbf(bfres(v0), bfres(v1));
            }
        }
}

// ---------------------------------------------------------------------------
// out = LayerNorm(inception + attended)
// ---------------------------------------------------------------------------
__global__ __launch_bounds__(256) void add_ln_kernel(
    const float* __restrict__ inc, const float* __restrict__ y,
    const float* __restrict__ gamma, const float* __restrict__ beta,
    float* __restrict__ out)
{
    const int row = blockIdx.x;
    const int tid = threadIdx.x;
    const size_t base = (size_t)row * NHID;

    float v = inc[base + tid] + y[base + tid];

    float s1 = v, s2 = v * v;
    #pragma unroll
    for (int o = 16; o; o >>= 1) {
        s1 += __shfl_xor_sync(0xFFFFFFFFu, s1, o);
        s2 += __shfl_xor_sync(0xFFFFFFFFu, s2, o);
    }
    __shared__ float r1[8], r2[8];
    if ((tid & 31) == 0) { r1[tid >> 5] = s1; r2[tid >> 5] = s2; }
    __syncthreads();
    float t1 = 0.f, t2 = 0.f;
    #pragma unroll
    for (int i = 0; i < 8; i++) { t1 += r1[i]; t2 += r2[i]; }

    float mu  = t1 * (1.0f / NHID);
    float var = t2 * (1.0f / NHID) - mu * mu;
    float rs  = rsqrtf(var + 1e-5f);
    out[base + tid] = (v - mu) * rs * gamma[tid] + beta[tid];
}

// ---------------------------------------------------------------------------
// Launch
// ---------------------------------------------------------------------------
extern "C" void kernel_launch(void* const* d_in, const int* in_sizes, int n_in,
                              void* d_out, int out_size)
{
    const float* x     = (const float*)d_in[0];
    const float* ea1   = (const float*)d_in[1];
    const float* ea2   = (const float*)d_in[2];
    const float* ln_w  = (const float*)d_in[3];
    const float* w1    = (const float*)d_in[4];
    const float* w2    = (const float*)d_in[5];
    const float* inw   = (const float*)d_in[6];   // [768,256] = [N,K]
    const float* inb   = (const float*)d_in[7];
    const float* outw  = (const float*)d_in[8];   // [256,256] = [N,K]
    const float* outb  = (const float*)d_in[9];
    const float* gamma = (const float*)d_in[10];
    const float* beta  = (const float*)d_in[11];
    const int*   ei1   = (const int*)d_in[12];
    const int*   ei2   = (const int*)d_in[13];
    float* out = (float*)d_out;

    const int n_edges = in_sizes[1];

    float *p_h1, *p_h2, *p_inc, *p_y;
    __nv_bfloat16 *p_xhi, *p_xlo, *p_ahi, *p_alo, *p_wThi, *p_wTlo;
    __nv_bfloat16 *p_wqhi, *p_wqlo, *p_wohi, *p_wolo, *p_qkvh, *p_qkvl;
    cudaGetSymbolAddress((void**)&p_h1, g_h1);
    cudaGetSymbolAddress((void**)&p_h2, g_h2);
    cudaGetSymbolAddress((void**)&p_inc, g_inc);
    cudaGetSymbolAddress((void**)&p_y, g_y);
    cudaGetSymbolAddress((void**)&p_xhi, g_xhi);
    cudaGetSymbolAddress((void**)&p_xlo, g_xlo);
    cudaGetSymbolAddress((void**)&p_ahi, g_ahi);
    cudaGetSymbolAddress((void**)&p_alo, g_alo);
    cudaGetSymbolAddress((void**)&p_wThi, g_wThi);
    cudaGetSymbolAddress((void**)&p_wTlo, g_wTlo);
    cudaGetSymbolAddress((void**)&p_wqhi, g_wqhi);
    cudaGetSymbolAddress((void**)&p_wqlo, g_wqlo);
    cudaGetSymbolAddress((void**)&p_wohi, g_wohi);
    cudaGetSymbolAddress((void**)&p_wolo, g_wolo);
    cudaGetSymbolAddress((void**)&p_qkvh, g_qkvh);
    cudaGetSymbolAddress((void**)&p_qkvl, g_qkvl);

    cudaFuncSetAttribute(hmma_gemm, cudaFuncAttributeMaxDynamicSharedMemorySize, SMEM_TOTAL);

    // x -> hi/lo
    cvt_hilo<<<(N_NODES * NFEAT + 255) / 256, 256>>>(x, p_xhi, p_xlo, N_NODES * NFEAT);

    // x0, h1, h2
    dim3 gA(NHID / 128, N_NODES / 128);
    cvt_hilo_T<<<(NFEAT * NHID + 255) / 256, 256>>>(ln_w, p_wThi, p_wTlo, NFEAT, NHID);
    hmma_gemm<<<gA, 256, SMEM_TOTAL>>>(p_xhi, p_xlo, p_wThi, p_wTlo, nullptr,
                                       p_inc, nullptr, nullptr, N_NODES, NHID, NFEAT);
    cvt_hilo_T<<<(NFEAT * NHID + 255) / 256, 256>>>(w1, p_wThi, p_wTlo, NFEAT, NHID);
    hmma_gemm<<<gA, 256, SMEM_TOTAL>>>(p_xhi, p_xlo, p_wThi, p_wTlo, nullptr,
                                       p_h1, nullptr, nullptr, N_NODES, NHID, NFEAT);
    cvt_hilo_T<<<(NFEAT * NHID + 255) / 256, 256>>>(w2, p_wThi, p_wTlo, NFEAT, NHID);
    hmma_gemm<<<gA, 256, SMEM_TOTAL>>>(p_xhi, p_xlo, p_wThi, p_wTlo, nullptr,
                                       p_h2, nullptr, nullptr, N_NODES, NHID, NFEAT);

    // scatter into inception
    int sblocks = (n_edges * 64 + 255) / 256;
    scatter_kernel<<<sblocks, 256>>>(ei1, ea1, p_h1, p_inc, n_edges);
    scatter_kernel<<<sblocks, 256>>>(ei2, ea2, p_h2, p_inc, n_edges);

    // qkv = inc @ in_proj_w^T + b  -> bf16 hi/lo directly
    cvt_hilo<<<(N_NODES * NHID + 255) / 256, 256>>>(p_inc, p_ahi, p_alo, N_NODES * NHID);
    cvt_hilo<<<(QKVDIM * NHID + 255) / 256, 256>>>(inw, p_wqhi, p_wqlo, QKVDIM * NHID);
    dim3 gQ(QKVDIM / 128, N_NODES / 128);
    hmma_gemm<<<gQ, 256, SMEM_TOTAL>>>(p_ahi, p_alo, p_wqhi, p_wqlo, inb,
                                       nullptr, p_qkvh, p_qkvl, N_NODES, QKVDIM, NHID);

    // attention -> ctx hi/lo (overwrites ahi/alo)
    dim3 gAtt(NPG / 128, HEADS, NGRAPHS);
    attn_mma<<<gAtt, 128>>>(p_qkvh, p_qkvl, p_ahi, p_alo);

    // y = ctx @ out_proj_w^T + b
    cvt_hilo<<<(NHID * NHID + 255) / 256, 256>>>(outw, p_wohi, p_wolo, NHID * NHID);
    hmma_gemm<<<gA, 256, SMEM_TOTAL>>>(p_ahi, p_alo, p_wohi, p_wolo, outb,
                                       p_y, nullptr, nullptr, N_NODES, NHID, NHID);

    // out = LN(inc + y)
    add_ln_kernel<<<N_NODES, 256>>>(p_inc, p_y, gamma, beta, out);
}

// round 12
// speedup vs baseline: 2.6197x; 1.0986x over previous
#include <cuda_runtime.h>
#include <cuda_bf16.h>
#include <math.h>
#include <cstdint>

// Problem constants
#define NFEAT    128
#define NHID     256
#define HEADS    4
#define DH       64
#define N_NODES  32768
#define N_EDGES  524288
#define NGRAPHS  64
#define NPG      512
#define QKVDIM   768
#define HCAT     768          // h0|h1|h2 concatenated
#define CAP      96           // max in-degree per node per edge set

// ---------------------------------------------------------------------------
// PTX helpers (sm_80+ compatible — toolchain lowers to .target sm_103, no tcgen05)
// ---------------------------------------------------------------------------
__device__ __forceinline__ uint32_t smem_u32(const void* p) {
    uint32_t a;
    asm("{ .reg .u64 t; cvta.to.shared.u64 t, %1; cvt.u32.u64 %0, t; }" : "=r"(a) : "l"(p));
    return a;
}

#define LDSM_X4(r, a)                                                          \
    asm volatile("ldmatrix.sync.aligned.m8n8.x4.shared.b16 {%0,%1,%2,%3}, [%4];" \
        : "=r"((r)[0]), "=r"((r)[1]), "=r"((r)[2]), "=r"((r)[3]) : "r"(a))

#define LDSM_X4_T(r, a)                                                        \
    asm volatile("ldmatrix.sync.aligned.m8n8.x4.trans.shared.b16 {%0,%1,%2,%3}, [%4];" \
        : "=r"((r)[0]), "=r"((r)[1]), "=r"((r)[2]), "=r"((r)[3]) : "r"(a))

__device__ __forceinline__ void mma16816(float* c, const uint32_t* a, const uint32_t* b) {
    asm volatile(
        "mma.sync.aligned.m16n8k16.row.col.f32.bf16.bf16.f32 "
        "{%0,%1,%2,%3}, {%4,%5,%6,%7}, {%8,%9}, {%0,%1,%2,%3};"
        : "+f"(c[0]), "+f"(c[1]), "+f"(c[2]), "+f"(c[3])
        : "r"(a[0]), "r"(a[1]), "r"(a[2]), "r"(a[3]), "r"(b[0]), "r"(b[1]));
}

#define SWZ(o) ((o) ^ (((o) >> 3) & 0x70))

__device__ __forceinline__ uint32_t packbf(float lo, float hi) {
    uint32_t r;
    asm("cvt.rn.bf16x2.f32 %0, %1, %2;" : "=r"(r) : "f"(hi), "f"(lo));
    return r;
}
__device__ __forceinline__ float bfres(float x) {
    __nv_bfloat16 h = __float2bfloat16(x);
    return x - __bfloat162float(h);
}

// ---------------------------------------------------------------------------
// Scratch
// ---------------------------------------------------------------------------
__device__ float g_h[N_NODES * HCAT];              // x0 | h1 | h2
__device__ float g_inc[N_NODES * NHID];
__device__ float g_y[N_NODES * NHID];
__device__ __nv_bfloat16 g_xhi[N_NODES * NFEAT];
__device__ __nv_bfloat16 g_xlo[N_NODES * NFEAT];
__device__ __nv_bfloat16 g_ahi[N_NODES * NHID];    // inc hi, then ctx hi
__device__ __nv_bfloat16 g_alo[N_NODES * NHID];
__device__ __nv_bfloat16 g_qkvh[N_NODES * QKVDIM];
__device__ __nv_bfloat16 g_qkvl[N_NODES * QKVDIM];
__device__ __nv_bfloat16 g_wcathi[HCAT * NFEAT];   // concat conv weights^T
__device__ __nv_bfloat16 g_wcatlo[HCAT * NFEAT];
__device__ __nv_bfloat16 g_wqhi[QKVDIM * NHID];
__device__ __nv_bfloat16 g_wqlo[QKVDIM * NHID];
__device__ __nv_bfloat16 g_wohi[NHID * NHID];
__device__ __nv_bfloat16 g_wolo[NHID * NHID];
// CSR buckets
__device__ int   g_cnt1[N_NODES];
__device__ int   g_cnt2[N_NODES];
__device__ uint2 g_el1[N_NODES * CAP];
__device__ uint2 g_el2[N_NODES * CAP];

// ---------------------------------------------------------------------------
// hi/lo split conversions
// ---------------------------------------------------------------------------
__global__ void cvt_hilo(const float* __restrict__ in,
                         __nv_bfloat16* __restrict__ hi, __nv_bfloat16* __restrict__ lo,
                         int n) {
    int i = blockIdx.x * 256 + threadIdx.x;
    if (i < n) {
        float x = in[i];
        __nv_bfloat16 h = __float2bfloat16(x);
        hi[i] = h;
        lo[i] = __float2bfloat16(x - __bfloat162float(h));
    }
}

// in [rows, cols] -> out [cols, rows] hi/lo
__global__ void cvt_hilo_T(const float* __restrict__ in,
                           __nv_bfloat16* __restrict__ hi, __nv_bfloat16* __restrict__ lo,
                           int rows, int cols) {
    int i = blockIdx.x * 256 + threadIdx.x;
    if (i < rows * cols) {
        int r = i / cols, c = i % cols;
        float x = in[i];
        __nv_bfloat16 h = __float2bfloat16(x);
        hi[c * rows + r] = h;
        lo[c * rows + r] = __float2bfloat16(x - __bfloat162float(h));
    }
}

// ---------------------------------------------------------------------------
// HMMA GEMM: C[M,N] = A[M,K] @ B[N,K]^T (+bias), hi/lo bf16 3-pass.
// CTA tile 128x128, BK=64, 8 warps (4m x 2n), warp tile 32x64.
// ---------------------------------------------------------------------------
#define OFF_AHI 0
#define OFF_ALO 16384
#define OFF_BHI 32768
#define OFF_BLO 49152
#define SMEM_TOTAL 65536

__device__ __forceinline__ void ldtile(const __nv_bfloat16* __restrict__ src,
                                       int r0, int k0, int ld, char* dst, int tid) {
    #pragma unroll
    for (int it = 0; it < 4; it++) {
        int i  = tid + it * 256;       // 0..1023
        int r  = i >> 3;               // 0..127
        int kc = i & 7;                // 16B chunk within 128B row
        uint32_t off = SWZ((uint32_t)(r * 128 + kc * 16));
        *(uint4*)(dst + off) = *(const uint4*)(src + (size_t)(r0 + r) * ld + k0 + kc * 8);
    }
}

__global__ __launch_bounds__(256)
void hmma_gemm(const __nv_bfloat16* __restrict__ Ahi, const __nv_bfloat16* __restrict__ Alo,
               const __nv_bfloat16* __restrict__ Bhi, const __nv_bfloat16* __restrict__ Blo,
               const float* __restrict__ bias,
               float* __restrict__ Cf,
               __nv_bfloat16* __restrict__ Chi, __nv_bfloat16* __restrict__ Clo,
               int M, int N, int K)
{
    extern __shared__ __align__(128) char smem[];
    const uint32_t sb = smem_u32(smem);
    const int tid  = threadIdx.x;
    const int wid  = tid >> 5;
    const int lane = tid & 31;
    const int row0 = blockIdx.y * 128;
    const int col0 = blockIdx.x * 128;
    const int wm   = (wid >> 1) * 32;
    const int wn   = (wid & 1) * 64;

    float acc[2][8][4];
    #pragma unroll
    for (int mt = 0; mt < 2; mt++)
        #pragma unroll
        for (int nt = 0; nt < 8; nt++)
            #pragma unroll
            for (int j = 0; j < 4; j++) acc[mt][nt][j] = 0.f;

    const int lg = lane >> 3;
    const int lr = lane & 7;
    const int a_r  = lr + (lg & 1) * 8;
    const int a_kb = (lg >> 1) * 16;
    const int b_r  = lr + (lg >> 1) * 8;
    const int b_kb = (lg & 1) * 16;

    for (int k0 = 0; k0 < K; k0 += 64) {
        ldtile(Ahi, row0, k0, K, smem + OFF_AHI, tid);
        ldtile(Alo, row0, k0, K, smem + OFF_ALO, tid);
        ldtile(Bhi, col0, k0, K, smem + OFF_BHI, tid);
        ldtile(Blo, col0, k0, K, smem + OFF_BLO, tid);
        __syncthreads();

        #pragma unroll
        for (int ks = 0; ks < 4; ks++) {
            const int kb = ks * 32;

            uint32_t ah[2][4], al[2][4];
            #pragma unroll
            for (int mt = 0; mt < 2; mt++) {
                uint32_t off = SWZ((uint32_t)((wm + mt * 16 + a_r) * 128 + kb + a_kb));
                LDSM_X4(ah[mt], sb + OFF_AHI + off);
                LDSM_X4(al[mt], sb + OFF_ALO + off);
            }
            uint32_t bh[4][4], bl[4][4];
            #pragma unroll
            for (int p = 0; p < 4; p++) {
                uint32_t off = SWZ((uint32_t)((wn + p * 16 + b_r) * 128 + kb + b_kb));
                LDSM_X4(bh[p], sb + OFF_BHI + off);
                LDSM_X4(bl[p], sb + OFF_BLO + off);
            }
            #pragma unroll
            for (int mt = 0; mt < 2; mt++)
                #pragma unroll
                for (int nt = 0; nt < 8; nt++) {
                    const uint32_t* Bh = &bh[nt >> 1][(nt & 1) * 2];
                    const uint32_t* Bl = &bl[nt >> 1][(nt & 1) * 2];
                    mma16816(acc[mt][nt], ah[mt], Bh);
                    mma16816(acc[mt][nt], ah[mt], Bl);
                    mma16816(acc[mt][nt], al[mt], Bh);
                }
        }
        __syncthreads();
    }

    const int cbase = col0 + wn + (lane & 3) * 2;
    const int rbase = row0 + wm + (lane >> 2);
    #pragma unroll
    for (int nt = 0; nt < 8; nt++) {
        float b0 = 0.f, b1 = 0.f;
        if (bias) { b0 = bias[cbase + nt * 8]; b1 = bias[cbase + nt * 8 + 1]; }
        #pragma unroll
        for (int mt = 0; mt < 2; mt++) {
            int r0 = rbase + mt * 16;
            float v00 = acc[mt][nt][0] + b0, v01 = acc[mt][nt][1] + b1;
            float v10 = acc[mt][nt][2] + b0, v11 = acc[mt][nt][3] + b1;
            if (Cf) {
                *(float2*)(Cf + (size_t)r0 * N + cbase + nt * 8)       = make_float2(v00, v01);
                *(float2*)(Cf + (size_t)(r0 + 8) * N + cbase + nt * 8) = make_float2(v10, v11);
            } else {
                size_t i0 = (size_t)r0 * N + cbase + nt * 8;
                size_t i1 = (size_t)(r0 + 8) * N + cbase + nt * 8;
                *(uint32_t*)(Chi + i0) = packbf(v00, v01);
                *(uint32_t*)(Chi + i1) = packbf(v10, v11);
                *(uint32_t*)(Clo + i0) = packbf(bfres(v00), bfres(v01));
                *(uint32_t*)(Clo + i1) = packbf(bfres(v10), bfres(v11));
            }
        }
    }
}

// ---------------------------------------------------------------------------
// CSR bucket build
// ---------------------------------------------------------------------------
__global__ void zero_cnt_kernel() {
    int i = blockIdx.x * 256 + threadIdx.x;
    if (i < N_NODES) { g_cnt1[i] = 0; g_cnt2[i] = 0; }
}

__global__ __launch_bounds__(256) void build_csr(
    const int* __restrict__ ei, const float* __restrict__ ea, int n_edges, int which)
{
    int e = blockIdx.x * 256 + threadIdx.x;
    if (e >= n_edges) return;
    int src = ei[e];
    int dst = ei[n_edges + e];
    int*   cnt = which ? g_cnt2 : g_cnt1;
    uint2* el  = which ? g_el2  : g_el1;
    int slot = atomicAdd(&cnt[dst], 1);
    if (slot < CAP)
        el[(size_t)dst * CAP + slot] = make_uint2((unsigned)src, __float_as_uint(ea[e]));
}

// ---------------------------------------------------------------------------
// Gather: inception[dst] = h0[dst] + sum ea1*h1[src] + sum ea2*h2[src]
// One block per dst node, 256 threads = feature lanes. Writes fp32 + bf16 hi/lo.
// ---------------------------------------------------------------------------
__global__ __launch_bounds__(256) void gather_kernel(
    const float* __restrict__ h, float* __restrict__ inc,
    __nv_bfloat16* __restrict__ hi, __nv_bfloat16* __restrict__ lo)
{
    const int dst = blockIdx.x;
    const int t   = threadIdx.x;

    __shared__ uint2 e1[CAP], e2[CAP];
    const int n1 = min(g_cnt1[dst], CAP);
    const int n2 = min(g_cnt2[dst], CAP);
    if (t < n1) e1[t] = g_el1[(size_t)dst * CAP + t];
    if (t < n2) e2[t] = g_el2[(size_t)dst * CAP + t];
    __syncthreads();

    float acc = h[(size_t)dst * HCAT + t];
    for (int i = 0; i < n1; i++) {
        float a = __uint_as_float(e1[i].y);
        acc = fmaf(a, __ldg(&h[(size_t)e1[i].x * HCAT + 256 + t]), acc);
    }
    for (int i = 0; i < n2; i++) {
        float a = __uint_as_float(e2[i].y);
        acc = fmaf(a, __ldg(&h[(size_t)e2[i].x * HCAT + 512 + t]), acc);
    }

    size_t idx = (size_t)dst * NHID + t;
    inc[idx] = acc;
    __nv_bfloat16 hh = __float2bfloat16(acc);
    hi[idx] = hh;
    lo[idx] = __float2bfloat16(acc - __bfloat162float(hh));
}

// ---------------------------------------------------------------------------
// Flash attention with mma.sync (FA2 register layout), hi/lo bf16 3-pass.
// ---------------------------------------------------------------------------
__global__ __launch_bounds__(128)
void attn_mma(const __nv_bfloat16* __restrict__ Qh, const __nv_bfloat16* __restrict__ Ql,
              __nv_bfloat16* __restrict__ Ch, __nv_bfloat16* __restrict__ Cl)
{
    __shared__ __align__(128) char sm[32768];
    char* Khp = sm;          char* Klp = sm + 8192;
    char* Vhp = sm + 16384;  char* Vlp = sm + 24576;
    const uint32_t sKh = smem_u32(Khp), sKl = smem_u32(Klp);
    const uint32_t sVh = smem_u32(Vhp), sVl = smem_u32(Vlp);

    const int qt = blockIdx.x, h = blockIdx.y, g = blockIdx.z;
    const int tid = threadIdx.x, wid = tid >> 5, lane = tid & 31;
    const int wm = wid * 32;
    const int node0 = g * NPG;
    const int q0 = node0 + qt * 128;
    const int qcol = h * DH;
    const int kcol = NHID + h * DH;
    const int vcol = 2 * NHID + h * DH;

    const int rl = lane >> 2;
    const int kp = (lane & 3) * 2;

    uint32_t qfh[2][4][4], qfl[2][4][4];
    #pragma unroll
    for (int mt = 0; mt < 2; mt++)
        #pragma unroll
        for (int ks = 0; ks < 4; ks++) {
            size_t base = (size_t)(q0 + wm + mt * 16 + rl) * QKVDIM + qcol + ks * 16 + kp;
            qfh[mt][ks][0] = *(const uint32_t*)(Qh + base);
            qfh[mt][ks][1] = *(const uint32_t*)(Qh + base + 8 * QKVDIM);
            qfh[mt][ks][2] = *(const uint32_t*)(Qh + base + 8);
            qfh[mt][ks][3] = *(const uint32_t*)(Qh + base + 8 * QKVDIM + 8);
            qfl[mt][ks][0] = *(const uint32_t*)(Ql + base);
            qfl[mt][ks][1] = *(const uint32_t*)(Ql + base + 8 * QKVDIM);
            qfl[mt][ks][2] = *(const uint32_t*)(Ql + base + 8);
            qfl[mt][ks][3] = *(const uint32_t*)(Ql + base + 8 * QKVDIM + 8);
        }

    float o[2][8][4];
    #pragma unroll
    for (int mt = 0; mt < 2; mt++)
        #pragma unroll
        for (int nt = 0; nt < 8; nt++)
            #pragma unroll
            for (int j = 0; j < 4; j++) o[mt][nt][j] = 0.f;
    float mst[2][2] = {{-1e30f, -1e30f}, {-1e30f, -1e30f}};
    float lst[2][2] = {{0.f, 0.f}, {0.f, 0.f}};

    const int lg = lane >> 3, lr = lane & 7;
    const int b_r  = lr + (lg >> 1) * 8;
    const int b_kb = (lg & 1) * 16;
    const int v_r  = lane & 15;
    const int v_cb = (lane >> 4) * 16;

    for (int kt = 0; kt < NPG / 64; kt++) {
        __syncthreads();
        #pragma unroll
        for (int it = 0; it < 4; it++) {
            int i = tid + it * 128;
            int row = i >> 3, c = i & 7;
            size_t gidx = (size_t)(node0 + kt * 64 + row) * QKVDIM;
            uint32_t off = SWZ((uint32_t)(row * 128 + c * 16));
            *(uint4*)(Khp + off) = *(const uint4*)(Qh + gidx + kcol + c * 8);
            *(uint4*)(Klp + off) = *(const uint4*)(Ql + gidx + kcol + c * 8);
            *(uint4*)(Vhp + off) = *(const uint4*)(Qh + gidx + vcol + c * 8);
            *(uint4*)(Vlp + off) = *(const uint4*)(Ql + gidx + vcol + c * 8);
        }
        __syncthreads();

        float s[2][8][4];
        #pragma unroll
        for (int mt = 0; mt < 2; mt++)
            #pragma unroll
            for (int nt = 0; nt < 8; nt++)
                #pragma unroll
                for (int j = 0; j < 4; j++) s[mt][nt][j] = 0.f;

        #pragma unroll
        for (int ks = 0; ks < 4; ks++) {
            uint32_t bh[4][4], bl[4][4];
            #pragma unroll
            for (int p = 0; p < 4; p++) {
                uint32_t off = SWZ((uint32_t)((p * 16 + b_r) * 128 + ks * 32 + b_kb));
                LDSM_X4(bh[p], sKh + off);
                LDSM_X4(bl[p], sKl + off);
            }
            #pragma unroll
            for (int mt = 0; mt < 2; mt++)
                #pragma unroll
                for (int nt = 0; nt < 8; nt++) {
                    const uint32_t* Bh = &bh[nt >> 1][(nt & 1) * 2];
                    const uint32_t* Bl = &bl[nt >> 1][(nt & 1) * 2];
                    mma16816(s[mt][nt], qfh[mt][ks], Bh);
                    mma16816(s[mt][nt], qfh[mt][ks], Bl);
                    mma16816(s[mt][nt], qfl[mt][ks], Bh);
                }
        }

        #pragma unroll
        for (int mt = 0; mt < 2; mt++)
            #pragma unroll
            for (int rh = 0; rh < 2; rh++) {
                const int i0 = rh * 2;
                float vmax = -1e30f;
                #pragma unroll
                for (int nt = 0; nt < 8; nt++)
                    vmax = fmaxf(vmax, fmaxf(s[mt][nt][i0], s[mt][nt][i0 + 1]));
                vmax = fmaxf(vmax, __shfl_xor_sync(0xFFFFFFFFu, vmax, 1));
                vmax = fmaxf(vmax, __shfl_xor_sync(0xFFFFFFFFu, vmax, 2));
                float mo = mst[mt][rh];
                float mn = fmaxf(mo, vmax);
                float sc = __expf((mo - mn) * 0.125f);
                float sum = 0.f;
                #pragma unroll
                for (int nt = 0; nt < 8; nt++) {
                    float p0 = __expf((s[mt][nt][i0]     - mn) * 0.125f);
                    float p1 = __expf((s[mt][nt][i0 + 1] - mn) * 0.125f);
                    s[mt][nt][i0] = p0; s[mt][nt][i0 + 1] = p1;
                    sum += p0 + p1;
                }
                sum += __shfl_xor_sync(0xFFFFFFFFu, sum, 1);
                sum += __shfl_xor_sync(0xFFFFFFFFu, sum, 2);
                lst[mt][rh] = lst[mt][rh] * sc + sum;
                mst[mt][rh] = mn;
                #pragma unroll
                for (int nt = 0; nt < 8; nt++) {
                    o[mt][nt][i0] *= sc;
                    o[mt][nt][i0 + 1] *= sc;
                }
            }

        #pragma unroll
        for (int ks = 0; ks < 4; ks++) {
            uint32_t vh[4][4], vl[4][4];
            #pragma unroll
            for (int d4 = 0; d4 < 4; d4++) {
                uint32_t off = SWZ((uint32_t)((ks * 16 + v_r) * 128 + d4 * 32 + v_cb));
                LDSM_X4_T(vh[d4], sVh + off);
                LDSM_X4_T(vl[d4], sVl + off);
            }
            #pragma unroll
            for (int mt = 0; mt < 2; mt++) {
                float a0 = s[mt][2 * ks][0],     a1 = s[mt][2 * ks][1];
                float a2 = s[mt][2 * ks][2],     a3 = s[mt][2 * ks][3];
                float c0 = s[mt][2 * ks + 1][0], c1 = s[mt][2 * ks + 1][1];
                float c2 = s[mt][2 * ks + 1][2], c3 = s[mt][2 * ks + 1][3];
                uint32_t pah[4], pal[4];
                pah[0] = packbf(a0, a1); pah[1] = packbf(a2, a3);
                pah[2] = packbf(c0, c1); pah[3] = packbf(c2, c3);
                pal[0] = packbf(bfres(a0), bfres(a1)); pal[1] = packbf(bfres(a2), bfres(a3));
                pal[2] = packbf(bfres(c0), bfres(c1)); pal[3] = packbf(bfres(c2), bfres(c3));
                #pragma unroll
                for (int nt = 0; nt < 8; nt++) {
                    const uint32_t* Bh = &vh[nt >> 1][(nt & 1) * 2];
                    const uint32_t* Bl = &vl[nt >> 1][(nt & 1) * 2];
                    mma16816(o[mt][nt], pah, Bh);
                    mma16816(o[mt][nt], pah, Bl);
                    mma16816(o[mt][nt], pal, Bh);
                }
            }
        }
    }

    #pragma unroll
    for (int mt = 0; mt < 2; mt++)
        #pragma unroll
        for (int rh = 0; rh < 2; rh++) {
            float inv = 1.0f / lst[mt][rh];
            int row = q0 + wm + mt * 16 + rh * 8 + rl;
            #pragma unroll
            for (int nt = 0; nt < 8; nt++) {
                float v0 = o[mt][nt][rh * 2]     * inv;
                float v1 = o[mt][nt][rh * 2 + 1] * inv;
                size_t idx = (size_t)row * NHID + qcol + nt * 8 + kp;
                *(uint32_t*)(Ch + idx) = packbf(v0, v1);
                *(uint32_t*)(Cl + idx) = packbf(bfres(v0), bfres(v1));
            }
        }
}

// ---------------------------------------------------------------------------
// out = LayerNorm(inception + attended)
// ---------------------------------------------------------------------------
__global__ __launch_bounds__(256) void add_ln_kernel(
    const float* __restrict__ inc, const float* __restrict__ y,
    const float* __restrict__ gamma, const float* __restrict__ beta,
    float* __restrict__ out)
{
    const int row = blockIdx.x;
    const int tid = threadIdx.x;
    const size_t base = (size_t)row * NHID;

    float v = inc[base + tid] + y[base + tid];

    float s1 = v, s2 = v * v;
    #pragma unroll
    for (int o = 16; o; o >>= 1) {
        s1 += __shfl_xor_sync(0xFFFFFFFFu, s1, o);
        s2 += __shfl_xor_sync(0xFFFFFFFFu, s2, o);
    }
    __shared__ float r1[8], r2[8];
    if ((tid & 31) == 0) { r1[tid >> 5] = s1; r2[tid >> 5] = s2; }
    __syncthreads();
    float t1 = 0.f, t2 = 0.f;
    #pragma unroll
    for (int i = 0; i < 8; i++) { t1 += r1[i]; t2 += r2[i]; }

    float mu  = t1 * (1.0f / NHID);
    float var = t2 * (1.0f / NHID) - mu * mu;
    float rs  = rsqrtf(var + 1e-5f);
    out[base + tid] = (v - mu) * rs * gamma[tid] + beta[tid];
}

// ---------------------------------------------------------------------------
// Launch
// ---------------------------------------------------------------------------
extern "C" void kernel_launch(void* const* d_in, const int* in_sizes, int n_in,
                              void* d_out, int out_size)
{
    const float* x     = (const float*)d_in[0];
    const float* ea1   = (const float*)d_in[1];
    const float* ea2   = (const float*)d_in[2];
    const float* ln_w  = (const float*)d_in[3];
    const float* w1    = (const float*)d_in[4];
    const float* w2    = (const float*)d_in[5];
    const float* inw   = (const float*)d_in[6];   // [768,256] = [N,K]
    const float* inb   = (const float*)d_in[7];
    const float* outw  = (const float*)d_in[8];   // [256,256] = [N,K]
    const float* outb  = (const float*)d_in[9];
    const float* gamma = (const float*)d_in[10];
    const float* beta  = (const float*)d_in[11];
    const int*   ei1   = (const int*)d_in[12];
    const int*   ei2   = (const int*)d_in[13];
    float* out = (float*)d_out;

    const int n_edges = in_sizes[1];

    float *p_h, *p_inc, *p_y;
    __nv_bfloat16 *p_xhi, *p_xlo, *p_ahi, *p_alo, *p_wchi, *p_wclo;
    __nv_bfloat16 *p_wqhi, *p_wqlo, *p_wohi, *p_wolo, *p_qkvh, *p_qkvl;
    cudaGetSymbolAddress((void**)&p_h, g_h);
    cudaGetSymbolAddress((void**)&p_inc, g_inc);
    cudaGetSymbolAddress((void**)&p_y, g_y);
    cudaGetSymbolAddress((void**)&p_xhi, g_xhi);
    cudaGetSymbolAddress((void**)&p_xlo, g_xlo);
    cudaGetSymbolAddress((void**)&p_ahi, g_ahi);
    cudaGetSymbolAddress((void**)&p_alo, g_alo);
    cudaGetSymbolAddress((void**)&p_wchi, g_wcathi);
    cudaGetSymbolAddress((void**)&p_wclo, g_wcatlo);
    cudaGetSymbolAddress((void**)&p_wqhi, g_wqhi);
    cudaGetSymbolAddress((void**)&p_wqlo, g_wqlo);
    cudaGetSymbolAddress((void**)&p_wohi, g_wohi);
    cudaGetSymbolAddress((void**)&p_wolo, g_wolo);
    cudaGetSymbolAddress((void**)&p_qkvh, g_qkvh);
    cudaGetSymbolAddress((void**)&p_qkvl, g_qkvl);

    cudaFuncSetAttribute(hmma_gemm, cudaFuncAttributeMaxDynamicSharedMemorySize, SMEM_TOTAL);

    // CSR bucket build (independent of GEMM work)
    zero_cnt_kernel<<<(N_NODES + 255) / 256, 256>>>();
    build_csr<<<(n_edges + 255) / 256, 256>>>(ei1, ea1, n_edges, 0);
    build_csr<<<(n_edges + 255) / 256, 256>>>(ei2, ea2, n_edges, 1);

    // x -> hi/lo ; concat conv weights^T -> hi/lo
    cvt_hilo<<<(N_NODES * NFEAT + 255) / 256, 256>>>(x, p_xhi, p_xlo, N_NODES * NFEAT);
    cvt_hilo_T<<<(NFEAT * NHID + 255) / 256, 256>>>(ln_w, p_wchi, p_wclo, NFEAT, NHID);
    cvt_hilo_T<<<(NFEAT * NHID + 255) / 256, 256>>>(w1, p_wchi + 256 * NFEAT,
                                                    p_wclo + 256 * NFEAT, NFEAT, NHID);
    cvt_hilo_T<<<(NFEAT * NHID + 255) / 256, 256>>>(w2, p_wchi + 512 * NFEAT,
                                                    p_wclo + 512 * NFEAT, NFEAT, NHID);

    // One fused conv GEMM: [x0 | h1 | h2] = x @ [ln_w | w1 | w2]
    dim3 gH(HCAT / 128, N_NODES / 128);
    hmma_gemm<<<gH, 256, SMEM_TOTAL>>>(p_xhi, p_xlo, p_wchi, p_wclo, nullptr,
                                       p_h, nullptr, nullptr, N_NODES, HCAT, NFEAT);

    // Pull-side gather: inception fp32 + hi/lo bf16
    gather_kernel<<<N_NODES, 256>>>(p_h, p_inc, p_ahi, p_alo);

    // qkv = inc @ in_proj_w^T + b  -> bf16 hi/lo directly
    cvt_hilo<<<(QKVDIM * NHID + 255) / 256, 256>>>(inw, p_wqhi, p_wqlo, QKVDIM * NHID);
    dim3 gQ(QKVDIM / 128, N_NODES / 128);
    hmma_gemm<<<gQ, 256, SMEM_TOTAL>>>(p_ahi, p_alo, p_wqhi, p_wqlo, inb,
                                       nullptr, p_qkvh, p_qkvl, N_NODES, QKVDIM, NHID);

    // attention -> ctx hi/lo (overwrites ahi/alo; inc hi/lo already consumed)
    dim3 gAtt(NPG / 128, HEADS, NGRAPHS);
    attn_mma<<<gAtt, 128>>>(p_qkvh, p_qkvl, p_ahi, p_alo);

    // y = ctx @ out_proj_w^T + b
    dim3 gA(NHID / 128, N_NODES / 128);
    cvt_hilo<<<(NHID * NHID + 255) / 256, 256>>>(outw, p_wohi, p_wolo, NHID * NHID);
    hmma_gemm<<<gA, 256, SMEM_TOTAL>>>(p_ahi, p_alo, p_wohi, p_wolo, outb,
                                       p_y, nullptr, nullptr, N_NODES, NHID, NHID);

    // out = LN(inc + y)
    add_ln_kernel<<<N_NODES, 256>>>(p_inc, p_y, gamma, beta, out);
}

// round 15
// speedup vs baseline: 2.9755x; 1.1358x over previous
#include <cuda_runtime.h>
#include <cuda_bf16.h>
#include <math.h>
#include <cstdint>

// Problem constants
#define NFEAT    128
#define NHID     256
#define HEADS    4
#define DH       64
#define N_NODES  32768
#define N_EDGES  524288
#define NGRAPHS  64
#define NPG      512
#define QKVDIM   768
#define HCAT     768          // h0|h1|h2 concatenated
#define CAP      96           // max in-degree per node per edge set

// ---------------------------------------------------------------------------
// PTX helpers (sm_80+ compatible — toolchain lowers to .target sm_103, no tcgen05)
// ---------------------------------------------------------------------------
__device__ __forceinline__ uint32_t smem_u32(const void* p) {
    uint32_t a;
    asm("{ .reg .u64 t; cvta.to.shared.u64 t, %1; cvt.u32.u64 %0, t; }" : "=r"(a) : "l"(p));
    return a;
}

#define LDSM_X4(r, a)                                                          \
    asm volatile("ldmatrix.sync.aligned.m8n8.x4.shared.b16 {%0,%1,%2,%3}, [%4];" \
        : "=r"((r)[0]), "=r"((r)[1]), "=r"((r)[2]), "=r"((r)[3]) : "r"(a))

#define LDSM_X4_T(r, a)                                                        \
    asm volatile("ldmatrix.sync.aligned.m8n8.x4.trans.shared.b16 {%0,%1,%2,%3}, [%4];" \
        : "=r"((r)[0]), "=r"((r)[1]), "=r"((r)[2]), "=r"((r)[3]) : "r"(a))

__device__ __forceinline__ void mma16816(float* c, const uint32_t* a, const uint32_t* b) {
    asm volatile(
        "mma.sync.aligned.m16n8k16.row.col.f32.bf16.bf16.f32 "
        "{%0,%1,%2,%3}, {%4,%5,%6,%7}, {%8,%9}, {%0,%1,%2,%3};"
        : "+f"(c[0]), "+f"(c[1]), "+f"(c[2]), "+f"(c[3])
        : "r"(a[0]), "r"(a[1]), "r"(a[2]), "r"(a[3]), "r"(b[0]), "r"(b[1]));
}

#define SWZ(o) ((o) ^ (((o) >> 3) & 0x70))

#define CP16(dst, src) \
    asm volatile("cp.async.cg.shared.global [%0], [%1], 16;" :: "r"(dst), "l"(src))
#define CP_COMMIT() asm volatile("cp.async.commit_group;" ::: "memory")
#define CP_WAIT(n)  asm volatile("cp.async.wait_group %0;" :: "n"(n) : "memory")

__device__ __forceinline__ uint32_t packbf(float lo, float hi) {
    uint32_t r;
    asm("cvt.rn.bf16x2.f32 %0, %1, %2;" : "=r"(r) : "f"(hi), "f"(lo));
    return r;
}
__device__ __forceinline__ float bfres(float x) {
    __nv_bfloat16 h = __float2bfloat16(x);
    return x - __bfloat162float(h);
}

// ---------------------------------------------------------------------------
// Scratch
// ---------------------------------------------------------------------------
__device__ float g_h[N_NODES * HCAT];              // x0 | h1 | h2
__device__ float g_inc[N_NODES * NHID];
__device__ float g_y[N_NODES * NHID];
__device__ __nv_bfloat16 g_xhi[N_NODES * NFEAT];
__device__ __nv_bfloat16 g_xlo[N_NODES * NFEAT];
__device__ __nv_bfloat16 g_ahi[N_NODES * NHID];    // inc hi, then ctx hi
__device__ __nv_bfloat16 g_alo[N_NODES * NHID];
__device__ __nv_bfloat16 g_qkvh[N_NODES * QKVDIM];
__device__ __nv_bfloat16 g_qkvl[N_NODES * QKVDIM];
__device__ __nv_bfloat16 g_wcathi[HCAT * NFEAT];   // concat conv weights^T
__device__ __nv_bfloat16 g_wcatlo[HCAT * NFEAT];
__device__ __nv_bfloat16 g_wqhi[QKVDIM * NHID];
__device__ __nv_bfloat16 g_wqlo[QKVDIM * NHID];
__device__ __nv_bfloat16 g_wohi[NHID * NHID];
__device__ __nv_bfloat16 g_wolo[NHID * NHID];
// CSR buckets
__device__ int   g_cnt1[N_NODES];
__device__ int   g_cnt2[N_NODES];
__device__ uint2 g_el1[N_NODES * CAP];
__device__ uint2 g_el2[N_NODES * CAP];

// ---------------------------------------------------------------------------
// hi/lo split conversions
// ---------------------------------------------------------------------------
__global__ void cvt_hilo(const float* __restrict__ in,
                         __nv_bfloat16* __restrict__ hi, __nv_bfloat16* __restrict__ lo,
                         int n) {
    int i = blockIdx.x * 256 + threadIdx.x;
    if (i < n) {
        float x = in[i];
        __nv_bfloat16 h = __float2bfloat16(x);
        hi[i] = h;
        lo[i] = __float2bfloat16(x - __bfloat162float(h));
    }
}

// in [rows, cols] -> out [cols, rows] hi/lo
__global__ void cvt_hilo_T(const float* __restrict__ in,
                           __nv_bfloat16* __restrict__ hi, __nv_bfloat16* __restrict__ lo,
                           int rows, int cols) {
    int i = blockIdx.x * 256 + threadIdx.x;
    if (i < rows * cols) {
        int r = i / cols, c = i % cols;
        float x = in[i];
        __nv_bfloat16 h = __float2bfloat16(x);
        hi[c * rows + r] = h;
        lo[c * rows + r] = __float2bfloat16(x - __bfloat162float(h));
    }
}

// ---------------------------------------------------------------------------
// HMMA GEMM: C[M,N] = A[M,K] @ B[N,K]^T (+bias), hi/lo bf16 3-pass.
// CTA tile 128x128, BK=64, 8 warps (4m x 2n), warp tile 32x64.
// 2-stage cp.async double-buffered pipeline (64KB per stage).
// ---------------------------------------------------------------------------
#define OFF_AHI 0
#define OFF_ALO 16384
#define OFF_BHI 32768
#define OFF_BLO 49152
#define STAGE_BYTES 65536
#define SMEM_TOTAL (2 * STAGE_BYTES)

__device__ __forceinline__ void ldtile_async(const __nv_bfloat16* __restrict__ src,
                                             int r0, int k0, int ld,
                                             uint32_t sdst, int tid) {
    #pragma unroll
    for (int it = 0; it < 4; it++) {
        int i  = tid + it * 256;       // 0..1023
        int r  = i >> 3;               // 0..127
        int kc = i & 7;                // 16B chunk within 128B row
        uint32_t off = SWZ((uint32_t)(r * 128 + kc * 16));
        CP16(sdst + off, src + (size_t)(r0 + r) * ld + k0 + kc * 8);
    }
}

__global__ __launch_bounds__(256)
void hmma_gemm(const __nv_bfloat16* __restrict__ Ahi, const __nv_bfloat16* __restrict__ Alo,
               const __nv_bfloat16* __restrict__ Bhi, const __nv_bfloat16* __restrict__ Blo,
               const float* __restrict__ bias,
               float* __restrict__ Cf,
               __nv_bfloat16* __restrict__ Chi, __nv_bfloat16* __restrict__ Clo,
               int M, int N, int K)
{
    extern __shared__ __align__(128) char smem[];
    const uint32_t sb = smem_u32(smem);
    const int tid  = threadIdx.x;
    const int wid  = tid >> 5;
    const int lane = tid & 31;
    const int row0 = blockIdx.y * 128;
    const int col0 = blockIdx.x * 128;
    const int wm   = (wid >> 1) * 32;
    const int wn   = (wid & 1) * 64;

    float acc[2][8][4];
    #pragma unroll
    for (int mt = 0; mt < 2; mt++)
        #pragma unroll
        for (int nt = 0; nt < 8; nt++)
            #pragma unroll
            for (int j = 0; j < 4; j++) acc[mt][nt][j] = 0.f;

    const int lg = lane >> 3;
    const int lr = lane & 7;
    const int a_r  = lr + (lg & 1) * 8;
    const int a_kb = (lg >> 1) * 16;
    const int b_r  = lr + (lg >> 1) * 8;
    const int b_kb = (lg & 1) * 16;

    const int nch = K >> 6;

    // Prefetch stage 0
    {
        uint32_t s0 = sb;
        ldtile_async(Ahi, row0, 0, K, s0 + OFF_AHI, tid);
        ldtile_async(Alo, row0, 0, K, s0 + OFF_ALO, tid);
        ldtile_async(Bhi, col0, 0, K, s0 + OFF_BHI, tid);
        ldtile_async(Blo, col0, 0, K, s0 + OFF_BLO, tid);
        CP_COMMIT();
    }

    for (int kc = 0; kc < nch; kc++) {
        const uint32_t scur = sb + (uint32_t)(kc & 1) * STAGE_BYTES;
        if (kc + 1 < nch) {
            const uint32_t snxt = sb + (uint32_t)((kc + 1) & 1) * STAGE_BYTES;
            const int kn = (kc + 1) << 6;
            ldtile_async(Ahi, row0, kn, K, snxt + OFF_AHI, tid);
            ldtile_async(Alo, row0, kn, K, snxt + OFF_ALO, tid);
            ldtile_async(Bhi, col0, kn, K, snxt + OFF_BHI, tid);
            ldtile_async(Blo, col0, kn, K, snxt + OFF_BLO, tid);
            CP_COMMIT();
            CP_WAIT(1);
        } else {
            CP_WAIT(0);
        }
        __syncthreads();

        #pragma unroll
        for (int ks = 0; ks < 4; ks++) {
            const int kb = ks * 32;

            uint32_t ah[2][4], al[2][4];
            #pragma unroll
            for (int mt = 0; mt < 2; mt++) {
                uint32_t off = SWZ((uint32_t)((wm + mt * 16 + a_r) * 128 + kb + a_kb));
                LDSM_X4(ah[mt], scur + OFF_AHI + off);
                LDSM_X4(al[mt], scur + OFF_ALO + off);
            }
            uint32_t bh[4][4], bl[4][4];
            #pragma unroll
            for (int p = 0; p < 4; p++) {
                uint32_t off = SWZ((uint32_t)((wn + p * 16 + b_r) * 128 + kb + b_kb));
                LDSM_X4(bh[p], scur + OFF_BHI + off);
                LDSM_X4(bl[p], scur + OFF_BLO + off);
            }
            #pragma unroll
            for (int mt = 0; mt < 2; mt++)
                #pragma unroll
                for (int nt = 0; nt < 8; nt++) {
                    const uint32_t* Bh = &bh[nt >> 1][(nt & 1) * 2];
                    const uint32_t* Bl = &bl[nt >> 1][(nt & 1) * 2];
                    mma16816(acc[mt][nt], ah[mt], Bh);
                    mma16816(acc[mt][nt], ah[mt], Bl);
                    mma16816(acc[mt][nt], al[mt], Bh);
                }
        }
        __syncthreads();   // protect stage being refilled next iteration
    }

    const int cbase = col0 + wn + (lane & 3) * 2;
    const int rbase = row0 + wm + (lane >> 2);
    #pragma unroll
    for (int nt = 0; nt < 8; nt++) {
        float b0 = 0.f, b1 = 0.f;
        if (bias) { b0 = bias[cbase + nt * 8]; b1 = bias[cbase + nt * 8 + 1]; }
        #pragma unroll
        for (int mt = 0; mt < 2; mt++) {
            int r0 = rbase + mt * 16;
            float v00 = acc[mt][nt][0] + b0, v01 = acc[mt][nt][1] + b1;
            float v10 = acc[mt][nt][2] + b0, v11 = acc[mt][nt][3] + b1;
            if (Cf) {
                *(float2*)(Cf + (size_t)r0 * N + cbase + nt * 8)       = make_float2(v00, v01);
                *(float2*)(Cf + (size_t)(r0 + 8) * N + cbase + nt * 8) = make_float2(v10, v11);
            } else {
                size_t i0 = (size_t)r0 * N + cbase + nt * 8;
                size_t i1 = (size_t)(r0 + 8) * N + cbase + nt * 8;
                *(uint32_t*)(Chi + i0) = packbf(v00, v01);
                *(uint32_t*)(Chi + i1) = packbf(v10, v11);
                *(uint32_t*)(Clo + i0) = packbf(bfres(v00), bfres(v01));
                *(uint32_t*)(Clo + i1) = packbf(bfres(v10), bfres(v11));
            }
        }
    }
}

// ---------------------------------------------------------------------------
// CSR bucket build
// ---------------------------------------------------------------------------
__global__ void zero_cnt_kernel() {
    int i = blockIdx.x * 256 + threadIdx.x;
    if (i < N_NODES) { g_cnt1[i] = 0; g_cnt2[i] = 0; }
}

__global__ __launch_bounds__(256) void build_csr(
    const int* __restrict__ ei, const float* __restrict__ ea, int n_edges, int which)
{
    int e = blockIdx.x * 256 + threadIdx.x;
    if (e >= n_edges) return;
    int src = ei[e];
    int dst = ei[n_edges + e];
    int*   cnt = which ? g_cnt2 : g_cnt1;
    uint2* el  = which ? g_el2  : g_el1;
    int slot = atomicAdd(&cnt[dst], 1);
    if (slot < CAP)
        el[(size_t)dst * CAP + slot] = make_uint2((unsigned)src, __float_as_uint(ea[e]));
}

// ---------------------------------------------------------------------------
// Gather: inception[dst] = h0[dst] + sum ea1*h1[src] + sum ea2*h2[src]
// One block per dst node, 256 threads = feature lanes. Writes fp32 + bf16 hi/lo.
// ---------------------------------------------------------------------------
__global__ __launch_bounds__(256) void gather_kernel(
    const float* __restrict__ h, float* __restrict__ inc,
    __nv_bfloat16* __restrict__ hi, __nv_bfloat16* __restrict__ lo)
{
    const int dst = blockIdx.x;
    const int t   = threadIdx.x;

    __shared__ uint2 e1[CAP], e2[CAP];
    const int n1 = min(g_cnt1[dst], CAP);
    const int n2 = min(g_cnt2[dst], CAP);
    if (t < n1) e1[t] = g_el1[(size_t)dst * CAP + t];
    if (t < n2) e2[t] = g_el2[(size_t)dst * CAP + t];
    __syncthreads();

    float acc = h[(size_t)dst * HCAT + t];
    for (int i = 0; i < n1; i++) {
        float a = __uint_as_float(e1[i].y);
        acc = fmaf(a, __ldg(&h[(size_t)e1[i].x * HCAT + 256 + t]), acc);
    }
    for (int i = 0; i < n2; i++) {
        float a = __uint_as_float(e2[i].y);
        acc = fmaf(a, __ldg(&h[(size_t)e2[i].x * HCAT + 512 + t]), acc);
    }

    size_t idx = (size_t)dst * NHID + t;
    inc[idx] = acc;
    __nv_bfloat16 hh = __float2bfloat16(acc);
    hi[idx] = hh;
    lo[idx] = __float2bfloat16(acc - __bfloat162float(hh));
}

// ---------------------------------------------------------------------------
// Flash attention with mma.sync (FA2 register layout), hi/lo bf16 3-pass.
// ---------------------------------------------------------------------------
__global__ __launch_bounds__(128)
void attn_mma(const __nv_bfloat16* __restrict__ Qh, const __nv_bfloat16* __restrict__ Ql,
              __nv_bfloat16* __restrict__ Ch, __nv_bfloat16* __restrict__ Cl)
{
    __shared__ __align__(128) char sm[32768];
    char* Khp = sm;          char* Klp = sm + 8192;
    char* Vhp = sm + 16384;  char* Vlp = sm + 24576;
    const uint32_t sKh = smem_u32(Khp), sKl = smem_u32(Klp);
    const uint32_t sVh = smem_u32(Vhp), sVl = smem_u32(Vlp);

    const int qt = blockIdx.x, h = blockIdx.y, g = blockIdx.z;
    const int tid = threadIdx.x, wid = tid >> 5, lane = tid & 31;
    const int wm = wid * 32;
    const int node0 = g * NPG;
    const int q0 = node0 + qt * 128;
    const int qcol = h * DH;
    const int kcol = NHID + h * DH;
    const int vcol = 2 * NHID + h * DH;

    const int rl = lane >> 2;
    const int kp = (lane & 3) * 2;

    uint32_t qfh[2][4][4], qfl[2][4][4];
    #pragma unroll
    for (int mt = 0; mt < 2; mt++)
        #pragma unroll
        for (int ks = 0; ks < 4; ks++) {
            size_t base = (size_t)(q0 + wm + mt * 16 + rl) * QKVDIM + qcol + ks * 16 + kp;
            qfh[mt][ks][0] = *(const uint32_t*)(Qh + base);
            qfh[mt][ks][1] = *(const uint32_t*)(Qh + base + 8 * QKVDIM);
            qfh[mt][ks][2] = *(const uint32_t*)(Qh + base + 8);
            qfh[mt][ks][3] = *(const uint32_t*)(Qh + base + 8 * QKVDIM + 8);
            qfl[mt][ks][0] = *(const uint32_t*)(Ql + base);
            qfl[mt][ks][1] = *(const uint32_t*)(Ql + base + 8 * QKVDIM);
            qfl[mt][ks][2] = *(const uint32_t*)(Ql + base + 8);
            qfl[mt][ks][3] = *(const uint32_t*)(Ql + base + 8 * QKVDIM + 8);
        }

    float o[2][8][4];
    #pragma unroll
    for (int mt = 0; mt < 2; mt++)
        #pragma unroll
        for (int nt = 0; nt < 8; nt++)
            #pragma unroll
            for (int j = 0; j < 4; j++) o[mt][nt][j] = 0.f;
    float mst[2][2] = {{-1e30f, -1e30f}, {-1e30f, -1e30f}};
    float lst[2][2] = {{0.f, 0.f}, {0.f, 0.f}};

    const int lg = lane >> 3, lr = lane & 7;
    const int b_r  = lr + (lg >> 1) * 8;
    const int b_kb = (lg & 1) * 16;
    const int v_r  = lane & 15;
    const int v_cb = (lane >> 4) * 16;

    for (int kt = 0; kt < NPG / 64; kt++) {
        __syncthreads();
        #pragma unroll
        for (int it = 0; it < 4; it++) {
            int i = tid + it * 128;
            int row = i >> 3, c = i & 7;
            size_t gidx = (size_t)(node0 + kt * 64 + row) * QKVDIM;
            uint32_t off = SWZ((uint32_t)(row * 128 + c * 16));
            *(uint4*)(Khp + off) = *(const uint4*)(Qh + gidx + kcol + c * 8);
            *(uint4*)(Klp + off) = *(const uint4*)(Ql + gidx + kcol + c * 8);
            *(uint4*)(Vhp + off) = *(const uint4*)(Qh + gidx + vcol + c * 8);
            *(uint4*)(Vlp + off) = *(const uint4*)(Ql + gidx + vcol + c * 8);
        }
        __syncthreads();

        float s[2][8][4];
        #pragma unroll
        for (int mt = 0; mt < 2; mt++)
            #pragma unroll
            for (int nt = 0; nt < 8; nt++)
                #pragma unroll
                for (int j = 0; j < 4; j++) s[mt][nt][j] = 0.f;

        #pragma unroll
        for (int ks = 0; ks < 4; ks++) {
            uint32_t bh[4][4], bl[4][4];
            #pragma unroll
            for (int p = 0; p < 4; p++) {
                uint32_t off = SWZ((uint32_t)((p * 16 + b_r) * 128 + ks * 32 + b_kb));
                LDSM_X4(bh[p], sKh + off);
                LDSM_X4(bl[p], sKl + off);
            }
            #pragma unroll
            for (int mt = 0; mt < 2; mt++)
                #pragma unroll
                for (int nt = 0; nt < 8; nt++) {
                    const uint32_t* Bh = &bh[nt >> 1][(nt & 1) * 2];
                    const uint32_t* Bl = &bl[nt >> 1][(nt & 1) * 2];
                    mma16816(s[mt][nt], qfh[mt][ks], Bh);
                    mma16816(s[mt][nt], qfh[mt][ks], Bl);
                    mma16816(s[mt][nt], qfl[mt][ks], Bh);
                }
        }

        #pragma unroll
        for (int mt = 0; mt < 2; mt++)
            #pragma unroll
            for (int rh = 0; rh < 2; rh++) {
                const int i0 = rh * 2;
                float vmax = -1e30f;
                #pragma unroll
                for (int nt = 0; nt < 8; nt++)
                    vmax = fmaxf(vmax, fmaxf(s[mt][nt][i0], s[mt][nt][i0 + 1]));
                vmax = fmaxf(vmax, __shfl_xor_sync(0xFFFFFFFFu, vmax, 1));
                vmax = fmaxf(vmax, __shfl_xor_sync(0xFFFFFFFFu, vmax, 2));
                float mo = mst[mt][rh];
                float mn = fmaxf(mo, vmax);
                float sc = __expf((mo - mn) * 0.125f);
                float sum = 0.f;
                #pragma unroll
                for (int nt = 0; nt < 8; nt++) {
                    float p0 = __expf((s[mt][nt][i0]     - mn) * 0.125f);
                    float p1 = __expf((s[mt][nt][i0 + 1] - mn) * 0.125f);
                    s[mt][nt][i0] = p0; s[mt][nt][i0 + 1] = p1;
                    sum += p0 + p1;
                }
                sum += __shfl_xor_sync(0xFFFFFFFFu, sum, 1);
                sum += __shfl_xor_sync(0xFFFFFFFFu, sum, 2);
                lst[mt][rh] = lst[mt][rh] * sc + sum;
                mst[mt][rh] = mn;
                #pragma unroll
                for (int nt = 0; nt < 8; nt++) {
                    o[mt][nt][i0] *= sc;
                    o[mt][nt][i0 + 1] *= sc;
                }
            }

        #pragma unroll
        for (int ks = 0; ks < 4; ks++) {
            uint32_t vh[4][4], vl[4][4];
            #pragma unroll
            for (int d4 = 0; d4 < 4; d4++) {
                uint32_t off = SWZ((uint32_t)((ks * 16 + v_r) * 128 + d4 * 32 + v_cb));
                LDSM_X4_T(vh[d4], sVh + off);
                LDSM_X4_T(vl[d4], sVl + off);
            }
            #pragma unroll
            for (int mt = 0; mt < 2; mt++) {
                float a0 = s[mt][2 * ks][0],     a1 = s[mt][2 * ks][1];
                float a2 = s[mt][2 * ks][2],     a3 = s[mt][2 * ks][3];
                float c0 = s[mt][2 * ks + 1][0], c1 = s[mt][2 * ks + 1][1];
                float c2 = s[mt][2 * ks + 1][2], c3 = s[mt][2 * ks + 1][3];
                uint32_t pah[4], pal[4];
                pah[0] = packbf(a0, a1); pah[1] = packbf(a2, a3);
                pah[2] = packbf(c0, c1); pah[3] = packbf(c2, c3);
                pal[0] = packbf(bfres(a0), bfres(a1)); pal[1] = packbf(bfres(a2), bfres(a3));
                pal[2] = packbf(bfres(c0), bfres(c1)); pal[3] = packbf(bfres(c2), bfres(c3));
                #pragma unroll
                for (int nt = 0; nt < 8; nt++) {
                    const uint32_t* Bh = &vh[nt >> 1][(nt & 1) * 2];
                    const uint32_t* Bl = &vl[nt >> 1][(nt & 1) * 2];
                    mma16816(o[mt][nt], pah, Bh);
                    mma16816(o[mt][nt], pah, Bl);
                    mma16816(o[mt][nt], pal, Bh);
                }
            }
        }
    }

    #pragma unroll
    for (int mt = 0; mt < 2; mt++)
        #pragma unroll
        for (int rh = 0; rh < 2; rh++) {
            float inv = 1.0f / lst[mt][rh];
            int row = q0 + wm + mt * 16 + rh * 8 + rl;
            #pragma unroll
            for (int nt = 0; nt < 8; nt++) {
                float v0 = o[mt][nt][rh * 2]     * inv;
                float v1 = o[mt][nt][rh * 2 + 1] * inv;
                size_t idx = (size_t)row * NHID + qcol + nt * 8 + kp;
                *(uint32_t*)(Ch + idx) = packbf(v0, v1);
                *(uint32_t*)(Cl + idx) = packbf(bfres(v0), bfres(v1));
            }
        }
}

// ---------------------------------------------------------------------------
// out = LayerNorm(inception + attended)
// ---------------------------------------------------------------------------
__global__ __launch_bounds__(256) void add_ln_kernel(
    const float* __restrict__ inc, const float* __restrict__ y,
    const float* __restrict__ gamma, const float* __restrict__ beta,
    float* __restrict__ out)
{
    const int row = blockIdx.x;
    const int tid = threadIdx.x;
    const size_t base = (size_t)row * NHID;

    float v = inc[base + tid] + y[base + tid];

    float s1 = v, s2 = v * v;
    #pragma unroll
    for (int o = 16; o; o >>= 1) {
        s1 += __shfl_xor_sync(0xFFFFFFFFu, s1, o);
        s2 += __shfl_xor_sync(0xFFFFFFFFu, s2, o);
    }
    __shared__ float r1[8], r2[8];
    if ((tid & 31) == 0) { r1[tid >> 5] = s1; r2[tid >> 5] = s2; }
    __syncthreads();
    float t1 = 0.f, t2 = 0.f;
    #pragma unroll
    for (int i = 0; i < 8; i++) { t1 += r1[i]; t2 += r2[i]; }

    float mu  = t1 * (1.0f / NHID);
    float var = t2 * (1.0f / NHID) - mu * mu;
    float rs  = rsqrtf(var + 1e-5f);
    out[base + tid] = (v - mu) * rs * gamma[tid] + beta[tid];
}

// ---------------------------------------------------------------------------
// Launch
// ---------------------------------------------------------------------------
extern "C" void kernel_launch(void* const* d_in, const int* in_sizes, int n_in,
                              void* d_out, int out_size)
{
    const float* x     = (const float*)d_in[0];
    const float* ea1   = (const float*)d_in[1];
    const float* ea2   = (const float*)d_in[2];
    const float* ln_w  = (const float*)d_in[3];
    const float* w1    = (const float*)d_in[4];
    const float* w2    = (const float*)d_in[5];
    const float* inw   = (const float*)d_in[6];   // [768,256] = [N,K]
    const float* inb   = (const float*)d_in[7];
    const float* outw  = (const float*)d_in[8];   // [256,256] = [N,K]
    const float* outb  = (const float*)d_in[9];
    const float* gamma = (const float*)d_in[10];
    const float* beta  = (const float*)d_in[11];
    const int*   ei1   = (const int*)d_in[12];
    const int*   ei2   = (const int*)d_in[13];
    float* out = (float*)d_out;

    const int n_edges = in_sizes[1];

    float *p_h, *p_inc, *p_y;
    __nv_bfloat16 *p_xhi, *p_xlo, *p_ahi, *p_alo, *p_wchi, *p_wclo;
    __nv_bfloat16 *p_wqhi, *p_wqlo, *p_wohi, *p_wolo, *p_qkvh, *p_qkvl;
    cudaGetSymbolAddress((void**)&p_h, g_h);
    cudaGetSymbolAddress((void**)&p_inc, g_inc);
    cudaGetSymbolAddress((void**)&p_y, g_y);
    cudaGetSymbolAddress((void**)&p_xhi, g_xhi);
    cudaGetSymbolAddress((void**)&p_xlo, g_xlo);
    cudaGetSymbolAddress((void**)&p_ahi, g_ahi);
    cudaGetSymbolAddress((void**)&p_alo, g_alo);
    cudaGetSymbolAddress((void**)&p_wchi, g_wcathi);
    cudaGetSymbolAddress((void**)&p_wclo, g_wcatlo);
    cudaGetSymbolAddress((void**)&p_wqhi, g_wqhi);
    cudaGetSymbolAddress((void**)&p_wqlo, g_wqlo);
    cudaGetSymbolAddress((void**)&p_wohi, g_wohi);
    cudaGetSymbolAddress((void**)&p_wolo, g_wolo);
    cudaGetSymbolAddress((void**)&p_qkvh, g_qkvh);
    cudaGetSymbolAddress((void**)&p_qkvl, g_qkvl);

    cudaFuncSetAttribute(hmma_gemm, cudaFuncAttributeMaxDynamicSharedMemorySize, SMEM_TOTAL);

    // CSR bucket build
    zero_cnt_kernel<<<(N_NODES + 255) / 256, 256>>>();
    build_csr<<<(n_edges + 255) / 256, 256>>>(ei1, ea1, n_edges, 0);
    build_csr<<<(n_edges + 255) / 256, 256>>>(ei2, ea2, n_edges, 1);

    // x -> hi/lo ; concat conv weights^T -> hi/lo
    cvt_hilo<<<(N_NODES * NFEAT + 255) / 256, 256>>>(x, p_xhi, p_xlo, N_NODES * NFEAT);
    cvt_hilo_T<<<(NFEAT * NHID + 255) / 256, 256>>>(ln_w, p_wchi, p_wclo, NFEAT, NHID);
    cvt_hilo_T<<<(NFEAT * NHID + 255) / 256, 256>>>(w1, p_wchi + 256 * NFEAT,
                                                    p_wclo + 256 * NFEAT, NFEAT, NHID);
    cvt_hilo_T<<<(NFEAT * NHID + 255) / 256, 256>>>(w2, p_wchi + 512 * NFEAT,
                                                    p_wclo + 512 * NFEAT, NFEAT, NHID);

    // One fused conv GEMM: [x0 | h1 | h2] = x @ [ln_w | w1 | w2]
    dim3 gH(HCAT / 128, N_NODES / 128);
    hmma_gemm<<<gH, 256, SMEM_TOTAL>>>(p_xhi, p_xlo, p_wchi, p_wclo, nullptr,
                                       p_h, nullptr, nullptr, N_NODES, HCAT, NFEAT);

    // Pull-side gather: inception fp32 + hi/lo bf16
    gather_kernel<<<N_NODES, 256>>>(p_h, p_inc, p_ahi, p_alo);

    // qkv = inc @ in_proj_w^T + b  -> bf16 hi/lo directly
    cvt_hilo<<<(QKVDIM * NHID + 255) / 256, 256>>>(inw, p_wqhi, p_wqlo, QKVDIM * NHID);
    dim3 gQ(QKVDIM / 128, N_NODES / 128);
    hmma_gemm<<<gQ, 256, SMEM_TOTAL>>>(p_ahi, p_alo, p_wqhi, p_wqlo, inb,
                                       nullptr, p_qkvh, p_qkvl, N_NODES, QKVDIM, NHID);

    // attention -> ctx hi/lo (overwrites ahi/alo)
    dim3 gAtt(NPG / 128, HEADS, NGRAPHS);
    attn_mma<<<gAtt, 128>>>(p_qkvh, p_qkvl, p_ahi, p_alo);

    // y = ctx @ out_proj_w^T + b
    dim3 gA(NHID / 128, N_NODES / 128);
    cvt_hilo<<<(NHID * NHID + 255) / 256, 256>>>(outw, p_wohi, p_wolo, NHID * NHID);
    hmma_gemm<<<gA, 256, SMEM_TOTAL>>>(p_ahi, p_alo, p_wohi, p_wolo, outb,
                                       p_y, nullptr, nullptr, N_NODES, NHID, NHID);

    // out = LN(inc + y)
    add_ln_kernel<<<N_NODES, 256>>>(p_inc, p_y, gamma, beta, out);
}

// round 17
// speedup vs baseline: 3.1975x; 1.0746x over previous
#include <cuda_runtime.h>
#include <cuda_bf16.h>
#include <math.h>
#include <cstdint>

// Problem constants
#define NFEAT    128
#define NHID     256
#define HEADS    4
#define DH       64
#define N_NODES  32768
#define N_EDGES  524288
#define NGRAPHS  64
#define NPG      512
#define QKVDIM   768
#define HCAT     768          // h0|h1|h2 concatenated
#define CAP      96           // max in-degree per node per edge set

// ---------------------------------------------------------------------------
// PTX helpers (sm_80+ compatible — toolchain lowers to .target sm_103, no tcgen05)
// ---------------------------------------------------------------------------
__device__ __forceinline__ uint32_t smem_u32(const void* p) {
    uint32_t a;
    asm("{ .reg .u64 t; cvta.to.shared.u64 t, %1; cvt.u32.u64 %0, t; }" : "=r"(a) : "l"(p));
    return a;
}

#define LDSM_X4(r, a)                                                          \
    asm volatile("ldmatrix.sync.aligned.m8n8.x4.shared.b16 {%0,%1,%2,%3}, [%4];" \
        : "=r"((r)[0]), "=r"((r)[1]), "=r"((r)[2]), "=r"((r)[3]) : "r"(a))

#define LDSM_X4_T(r, a)                                                        \
    asm volatile("ldmatrix.sync.aligned.m8n8.x4.trans.shared.b16 {%0,%1,%2,%3}, [%4];" \
        : "=r"((r)[0]), "=r"((r)[1]), "=r"((r)[2]), "=r"((r)[3]) : "r"(a))

__device__ __forceinline__ void mma16816(float* c, const uint32_t* a, const uint32_t* b) {
    asm volatile(
        "mma.sync.aligned.m16n8k16.row.col.f32.bf16.bf16.f32 "
        "{%0,%1,%2,%3}, {%4,%5,%6,%7}, {%8,%9}, {%0,%1,%2,%3};"
        : "+f"(c[0]), "+f"(c[1]), "+f"(c[2]), "+f"(c[3])
        : "r"(a[0]), "r"(a[1]), "r"(a[2]), "r"(a[3]), "r"(b[0]), "r"(b[1]));
}

#define SWZ(o) ((o) ^ (((o) >> 3) & 0x70))

#define CP16(dst, src) \
    asm volatile("cp.async.cg.shared.global [%0], [%1], 16;" :: "r"(dst), "l"(src))
#define CP_COMMIT() asm volatile("cp.async.commit_group;" ::: "memory")
#define CP_WAIT(n)  asm volatile("cp.async.wait_group %0;" :: "n"(n) : "memory")

__device__ __forceinline__ uint32_t packbf(float lo, float hi) {
    uint32_t r;
    asm("cvt.rn.bf16x2.f32 %0, %1, %2;" : "=r"(r) : "f"(hi), "f"(lo));
    return r;
}
__device__ __forceinline__ float bfres(float x) {
    __nv_bfloat16 h = __float2bfloat16(x);
    return x - __bfloat162float(h);
}

// ---------------------------------------------------------------------------
// Scratch
// ---------------------------------------------------------------------------
__device__ float g_h[N_NODES * HCAT];              // x0 | h1 | h2
__device__ float g_inc[N_NODES * NHID];
__device__ float g_y[N_NODES * NHID];
__device__ __nv_bfloat16 g_xhi[N_NODES * NFEAT];
__device__ __nv_bfloat16 g_xlo[N_NODES * NFEAT];
__device__ __nv_bfloat16 g_ahi[N_NODES * NHID];    // inc hi, then ctx hi
__device__ __nv_bfloat16 g_alo[N_NODES * NHID];
__device__ __nv_bfloat16 g_qkvh[N_NODES * QKVDIM];
__device__ __nv_bfloat16 g_qkvl[N_NODES * QKVDIM];
__device__ __nv_bfloat16 g_wcathi[HCAT * NFEAT];   // concat conv weights^T
__device__ __nv_bfloat16 g_wcatlo[HCAT * NFEAT];
__device__ __nv_bfloat16 g_wqhi[QKVDIM * NHID];
__device__ __nv_bfloat16 g_wqlo[QKVDIM * NHID];
__device__ __nv_bfloat16 g_wohi[NHID * NHID];
__device__ __nv_bfloat16 g_wolo[NHID * NHID];
// CSR buckets
__device__ int   g_cnt1[N_NODES];
__device__ int   g_cnt2[N_NODES];
__device__ uint2 g_el1[N_NODES * CAP];
__device__ uint2 g_el2[N_NODES * CAP];

// ---------------------------------------------------------------------------
// hi/lo split conversions (vectorized: 4 elems/thread)
// ---------------------------------------------------------------------------
__global__ void cvt_hilo4(const float* __restrict__ in,
                          __nv_bfloat16* __restrict__ hi, __nv_bfloat16* __restrict__ lo,
                          int n4) {
    int i = blockIdx.x * 256 + threadIdx.x;
    if (i < n4) {
        float4 v = ((const float4*)in)[i];
        uint32_t h0 = packbf(v.x, v.y);
        uint32_t h1 = packbf(v.z, v.w);
        // residuals
        __nv_bfloat162 hh0 = *(__nv_bfloat162*)&h0;
        __nv_bfloat162 hh1 = *(__nv_bfloat162*)&h1;
        uint32_t l0 = packbf(v.x - __bfloat162float(hh0.x), v.y - __bfloat162float(hh0.y));
        uint32_t l1 = packbf(v.z - __bfloat162float(hh1.x), v.w - __bfloat162float(hh1.y));
        ((uint2*)hi)[i] = make_uint2(h0, h1);
        ((uint2*)lo)[i] = make_uint2(l0, l1);
    }
}

// in [rows, cols] -> out [cols, rows] hi/lo (small weight transposes)
__global__ void cvt_hilo_T(const float* __restrict__ in,
                           __nv_bfloat16* __restrict__ hi, __nv_bfloat16* __restrict__ lo,
                           int rows, int cols) {
    int i = blockIdx.x * 256 + threadIdx.x;
    if (i < rows * cols) {
        int r = i / cols, c = i % cols;
        float x = in[i];
        __nv_bfloat16 h = __float2bfloat16(x);
        hi[c * rows + r] = h;
        lo[c * rows + r] = __float2bfloat16(x - __bfloat162float(h));
    }
}

// ---------------------------------------------------------------------------
// HMMA GEMM: C[M,N] = A[M,K] @ B[N,K]^T (+bias), hi/lo bf16 3-pass.
// CTA tile 64x128, BK=64, 8 warps (2m x 4n), warp tile 32x32.
// 2-stage cp.async pipeline, 48KB/stage, 96KB/CTA -> 2 CTAs/SM.
// ---------------------------------------------------------------------------
#define OFF_AHI 0
#define OFF_ALO 8192
#define OFF_BHI 16384
#define OFF_BLO 32768
#define STAGE_BYTES 49152
#define SMEM_TOTAL (2 * STAGE_BYTES)

// A tile: 64 rows x 128B ; B tile: 128 rows x 128B
__device__ __forceinline__ void ldtile_a(const __nv_bfloat16* __restrict__ src,
                                         int r0, int k0, int ld,
                                         uint32_t sdst, int tid) {
    #pragma unroll
    for (int it = 0; it < 2; it++) {
        int i  = tid + it * 256;       // 0..511
        int r  = i >> 3;               // 0..63
        int kc = i & 7;
        uint32_t off = SWZ((uint32_t)(r * 128 + kc * 16));
        CP16(sdst + off, src + (size_t)(r0 + r) * ld + k0 + kc * 8);
    }
}
__device__ __forceinline__ void ldtile_b(const __nv_bfloat16* __restrict__ src,
                                         int r0, int k0, int ld,
                                         uint32_t sdst, int tid) {
    #pragma unroll
    for (int it = 0; it < 4; it++) {
        int i  = tid + it * 256;       // 0..1023
        int r  = i >> 3;               // 0..127
        int kc = i & 7;
        uint32_t off = SWZ((uint32_t)(r * 128 + kc * 16));
        CP16(sdst + off, src + (size_t)(r0 + r) * ld + k0 + kc * 8);
    }
}

__global__ __launch_bounds__(256, 2)
void hmma_gemm(const __nv_bfloat16* __restrict__ Ahi, const __nv_bfloat16* __restrict__ Alo,
               const __nv_bfloat16* __restrict__ Bhi, const __nv_bfloat16* __restrict__ Blo,
               const float* __restrict__ bias,
               float* __restrict__ Cf,
               __nv_bfloat16* __restrict__ Chi, __nv_bfloat16* __restrict__ Clo,
               int M, int N, int K)
{
    extern __shared__ __align__(128) char smem[];
    const uint32_t sb = smem_u32(smem);
    const int tid  = threadIdx.x;
    const int wid  = tid >> 5;
    const int lane = tid & 31;
    const int row0 = blockIdx.y * 64;
    const int col0 = blockIdx.x * 128;
    const int wm   = (wid >> 2) * 32;       // 2 m-warps
    const int wn   = (wid & 3) * 32;        // 4 n-warps

    float acc[2][4][4];
    #pragma unroll
    for (int mt = 0; mt < 2; mt++)
        #pragma unroll
        for (int nt = 0; nt < 4; nt++)
            #pragma unroll
            for (int j = 0; j < 4; j++) acc[mt][nt][j] = 0.f;

    const int lg = lane >> 3;
    const int lr = lane & 7;
    const int a_r  = lr + (lg & 1) * 8;
    const int a_kb = (lg >> 1) * 16;
    const int b_r  = lr + (lg >> 1) * 8;
    const int b_kb = (lg & 1) * 16;

    const int nch = K >> 6;

    // Prefetch stage 0
    {
        uint32_t s0 = sb;
        ldtile_a(Ahi, row0, 0, K, s0 + OFF_AHI, tid);
        ldtile_a(Alo, row0, 0, K, s0 + OFF_ALO, tid);
        ldtile_b(Bhi, col0, 0, K, s0 + OFF_BHI, tid);
        ldtile_b(Blo, col0, 0, K, s0 + OFF_BLO, tid);
        CP_COMMIT();
    }

    for (int kc = 0; kc < nch; kc++) {
        const uint32_t scur = sb + (uint32_t)(kc & 1) * STAGE_BYTES;
        if (kc + 1 < nch) {
            const uint32_t snxt = sb + (uint32_t)((kc + 1) & 1) * STAGE_BYTES;
            const int kn = (kc + 1) << 6;
            ldtile_a(Ahi, row0, kn, K, snxt + OFF_AHI, tid);
            ldtile_a(Alo, row0, kn, K, snxt + OFF_ALO, tid);
            ldtile_b(Bhi, col0, kn, K, snxt + OFF_BHI, tid);
            ldtile_b(Blo, col0, kn, K, snxt + OFF_BLO, tid);
            CP_COMMIT();
            CP_WAIT(1);
        } else {
            CP_WAIT(0);
        }
        __syncthreads();

        #pragma unroll
        for (int ks = 0; ks < 4; ks++) {
            const int kb = ks * 32;

            uint32_t ah[2][4], al[2][4];
            #pragma unroll
            for (int mt = 0; mt < 2; mt++) {
                uint32_t off = SWZ((uint32_t)((wm + mt * 16 + a_r) * 128 + kb + a_kb));
                LDSM_X4(ah[mt], scur + OFF_AHI + off);
                LDSM_X4(al[mt], scur + OFF_ALO + off);
            }
            uint32_t bh[2][4], bl[2][4];
            #pragma unroll
            for (int p = 0; p < 2; p++) {
                uint32_t off = SWZ((uint32_t)((wn + p * 16 + b_r) * 128 + kb + b_kb));
                LDSM_X4(bh[p], scur + OFF_BHI + off);
                LDSM_X4(bl[p], scur + OFF_BLO + off);
            }
            #pragma unroll
            for (int mt = 0; mt < 2; mt++)
                #pragma unroll
                for (int nt = 0; nt < 4; nt++) {
                    const uint32_t* Bh = &bh[nt >> 1][(nt & 1) * 2];
                    const uint32_t* Bl = &bl[nt >> 1][(nt & 1) * 2];
                    mma16816(acc[mt][nt], ah[mt], Bh);
                    mma16816(acc[mt][nt], ah[mt], Bl);
                    mma16816(acc[mt][nt], al[mt], Bh);
                }
        }
        __syncthreads();   // protect stage being refilled next iteration
    }

    const int cbase = col0 + wn + (lane & 3) * 2;
    const int rbase = row0 + wm + (lane >> 2);
    #pragma unroll
    for (int nt = 0; nt < 4; nt++) {
        float b0 = 0.f, b1 = 0.f;
        if (bias) { b0 = bias[cbase + nt * 8]; b1 = bias[cbase + nt * 8 + 1]; }
        #pragma unroll
        for (int mt = 0; mt < 2; mt++) {
            int r0 = rbase + mt * 16;
            float v00 = acc[mt][nt][0] + b0, v01 = acc[mt][nt][1] + b1;
            float v10 = acc[mt][nt][2] + b0, v11 = acc[mt][nt][3] + b1;
            if (Cf) {
                *(float2*)(Cf + (size_t)r0 * N + cbase + nt * 8)       = make_float2(v00, v01);
                *(float2*)(Cf + (size_t)(r0 + 8) * N + cbase + nt * 8) = make_float2(v10, v11);
            } else {
                size_t i0 = (size_t)r0 * N + cbase + nt * 8;
                size_t i1 = (size_t)(r0 + 8) * N + cbase + nt * 8;
                *(uint32_t*)(Chi + i0) = packbf(v00, v01);
                *(uint32_t*)(Chi + i1) = packbf(v10, v11);
                *(uint32_t*)(Clo + i0) = packbf(bfres(v00), bfres(v01));
                *(uint32_t*)(Clo + i1) = packbf(bfres(v10), bfres(v11));
            }
        }
    }
}

// ---------------------------------------------------------------------------
// CSR bucket build
// ---------------------------------------------------------------------------
__global__ void zero_cnt_kernel() {
    int i = blockIdx.x * 256 + threadIdx.x;
    if (i < N_NODES) { g_cnt1[i] = 0; g_cnt2[i] = 0; }
}

__global__ __launch_bounds__(256) void build_csr(
    const int* __restrict__ ei, const float* __restrict__ ea, int n_edges, int which)
{
    int e = blockIdx.x * 256 + threadIdx.x;
    if (e >= n_edges) return;
    int src = ei[e];
    int dst = ei[n_edges + e];
    int*   cnt = which ? g_cnt2 : g_cnt1;
    uint2* el  = which ? g_el2  : g_el1;
    int slot = atomicAdd(&cnt[dst], 1);
    if (slot < CAP)
        el[(size_t)dst * CAP + slot] = make_uint2((unsigned)src, __float_as_uint(ea[e]));
}

// ---------------------------------------------------------------------------
// Gather: inception[dst] = h0[dst] + sum ea1*h1[src] + sum ea2*h2[src]
// ---------------------------------------------------------------------------
__global__ __launch_bounds__(256) void gather_kernel(
    const float* __restrict__ h, float* __restrict__ inc,
    __nv_bfloat16* __restrict__ hi, __nv_bfloat16* __restrict__ lo)
{
    const int dst = blockIdx.x;
    const int t   = threadIdx.x;

    __shared__ uint2 e1[CAP], e2[CAP];
    const int n1 = min(g_cnt1[dst], CAP);
    const int n2 = min(g_cnt2[dst], CAP);
    if (t < n1) e1[t] = g_el1[(size_t)dst * CAP + t];
    if (t < n2) e2[t] = g_el2[(size_t)dst * CAP + t];
    __syncthreads();

    float acc = h[(size_t)dst * HCAT + t];
    for (int i = 0; i < n1; i++) {
        float a = __uint_as_float(e1[i].y);
        acc = fmaf(a, __ldg(&h[(size_t)e1[i].x * HCAT + 256 + t]), acc);
    }
    for (int i = 0; i < n2; i++) {
        float a = __uint_as_float(e2[i].y);
        acc = fmaf(a, __ldg(&h[(size_t)e2[i].x * HCAT + 512 + t]), acc);
    }

    size_t idx = (size_t)dst * NHID + t;
    inc[idx] = acc;
    __nv_bfloat16 hh = __float2bfloat16(acc);
    hi[idx] = hh;
    lo[idx] = __float2bfloat16(acc - __bfloat162float(hh));
}

// ---------------------------------------------------------------------------
// Flash attention with mma.sync (FA2 register layout), hi/lo bf16 3-pass.
// ---------------------------------------------------------------------------
__global__ __launch_bounds__(128)
void attn_mma(const __nv_bfloat16* __restrict__ Qh, const __nv_bfloat16* __restrict__ Ql,
              __nv_bfloat16* __restrict__ Ch, __nv_bfloat16* __restrict__ Cl)
{
    __shared__ __align__(128) char sm[32768];
    char* Khp = sm;          char* Klp = sm + 8192;
    char* Vhp = sm + 16384;  char* Vlp = sm + 24576;
    const uint32_t sKh = smem_u32(Khp), sKl = smem_u32(Klp);
    const uint32_t sVh = smem_u32(Vhp), sVl = smem_u32(Vlp);

    const int qt = blockIdx.x, h = blockIdx.y, g = blockIdx.z;
    const int tid = threadIdx.x, wid = tid >> 5, lane = tid & 31;
    const int wm = wid * 32;
    const int node0 = g * NPG;
    const int q0 = node0 + qt * 128;
    const int qcol = h * DH;
    const int kcol = NHID + h * DH;
    const int vcol = 2 * NHID + h * DH;

    const int rl = lane >> 2;
    const int kp = (lane & 3) * 2;

    uint32_t qfh[2][4][4], qfl[2][4][4];
    #pragma unroll
    for (int mt = 0; mt < 2; mt++)
        #pragma unroll
        for (int ks = 0; ks < 4; ks++) {
            size_t base = (size_t)(q0 + wm + mt * 16 + rl) * QKVDIM + qcol + ks * 16 + kp;
            qfh[mt][ks][0] = *(const uint32_t*)(Qh + base);
            qfh[mt][ks][1] = *(const uint32_t*)(Qh + base + 8 * QKVDIM);
            qfh[mt][ks][2] = *(const uint32_t*)(Qh + base + 8);
            qfh[mt][ks][3] = *(const uint32_t*)(Qh + base + 8 * QKVDIM + 8);
            qfl[mt][ks][0] = *(const uint32_t*)(Ql + base);
            qfl[mt][ks][1] = *(const uint32_t*)(Ql + base + 8 * QKVDIM);
            qfl[mt][ks][2] = *(const uint32_t*)(Ql + base + 8);
            qfl[mt][ks][3] = *(const uint32_t*)(Ql + base + 8 * QKVDIM + 8);
        }

    float o[2][8][4];
    #pragma unroll
    for (int mt = 0; mt < 2; mt++)
        #pragma unroll
        for (int nt = 0; nt < 8; nt++)
            #pragma unroll
            for (int j = 0; j < 4; j++) o[mt][nt][j] = 0.f;
    float mst[2][2] = {{-1e30f, -1e30f}, {-1e30f, -1e30f}};
    float lst[2][2] = {{0.f, 0.f}, {0.f, 0.f}};

    const int lg = lane >> 3, lr = lane & 7;
    const int b_r  = lr + (lg >> 1) * 8;
    const int b_kb = (lg & 1) * 16;
    const int v_r  = lane & 15;
    const int v_cb = (lane >> 4) * 16;

    for (int kt = 0; kt < NPG / 64; kt++) {
        __syncthreads();
        #pragma unroll
        for (int it = 0; it < 4; it++) {
            int i = tid + it * 128;
            int row = i >> 3, c = i & 7;
            size_t gidx = (size_t)(node0 + kt * 64 + row) * QKVDIM;
            uint32_t off = SWZ((uint32_t)(row * 128 + c * 16));
            *(uint4*)(Khp + off) = *(const uint4*)(Qh + gidx + kcol + c * 8);
            *(uint4*)(Klp + off) = *(const uint4*)(Ql + gidx + kcol + c * 8);
            *(uint4*)(Vhp + off) = *(const uint4*)(Qh + gidx + vcol + c * 8);
            *(uint4*)(Vlp + off) = *(const uint4*)(Ql + gidx + vcol + c * 8);
        }
        __syncthreads();

        float s[2][8][4];
        #pragma unroll
        for (int mt = 0; mt < 2; mt++)
            #pragma unroll
            for (int nt = 0; nt < 8; nt++)
                #pragma unroll
                for (int j = 0; j < 4; j++) s[mt][nt][j] = 0.f;

        #pragma unroll
        for (int ks = 0; ks < 4; ks++) {
            uint32_t bh[4][4], bl[4][4];
            #pragma unroll
            for (int p = 0; p < 4; p++) {
                uint32_t off = SWZ((uint32_t)((p * 16 + b_r) * 128 + ks * 32 + b_kb));
                LDSM_X4(bh[p], sKh + off);
                LDSM_X4(bl[p], sKl + off);
            }
            #pragma unroll
            for (int mt = 0; mt < 2; mt++)
                #pragma unroll
                for (int nt = 0; nt < 8; nt++) {
                    const uint32_t* Bh = &bh[nt >> 1][(nt & 1) * 2];
                    const uint32_t* Bl = &bl[nt >> 1][(nt & 1) * 2];
                    mma16816(s[mt][nt], qfh[mt][ks], Bh);
                    mma16816(s[mt][nt], qfh[mt][ks], Bl);
                    mma16816(s[mt][nt], qfl[mt][ks], Bh);
                }
        }

        #pragma unroll
        for (int mt = 0; mt < 2; mt++)
            #pragma unroll
            for (int rh = 0; rh < 2; rh++) {
                const int i0 = rh * 2;
                float vmax = -1e30f;
                #pragma unroll
                for (int nt = 0; nt < 8; nt++)
                    vmax = fmaxf(vmax, fmaxf(s[mt][nt][i0], s[mt][nt][i0 + 1]));
                vmax = fmaxf(vmax, __shfl_xor_sync(0xFFFFFFFFu, vmax, 1));
                vmax = fmaxf(vmax, __shfl_xor_sync(0xFFFFFFFFu, vmax, 2));
                float mo = mst[mt][rh];
                float mn = fmaxf(mo, vmax);
                float sc = __expf((mo - mn) * 0.125f);
                float sum = 0.f;
                #pragma unroll
                for (int nt = 0; nt < 8; nt++) {
                    float p0 = __expf((s[mt][nt][i0]     - mn) * 0.125f);
                    float p1 = __expf((s[mt][nt][i0 + 1] - mn) * 0.125f);
                    s[mt][nt][i0] = p0; s[mt][nt][i0 + 1] = p1;
                    sum += p0 + p1;
                }
                sum += __shfl_xor_sync(0xFFFFFFFFu, sum, 1);
                sum += __shfl_xor_sync(0xFFFFFFFFu, sum, 2);
                lst[mt][rh] = lst[mt][rh] * sc + sum;
                mst[mt][rh] = mn;
                #pragma unroll
                for (int nt = 0; nt < 8; nt++) {
                    o[mt][nt][i0] *= sc;
                    o[mt][nt][i0 + 1] *= sc;
                }
            }

        #pragma unroll
        for (int ks = 0; ks < 4; ks++) {
            uint32_t vh[4][4], vl[4][4];
            #pragma unroll
            for (int d4 = 0; d4 < 4; d4++) {
                uint32_t off = SWZ((uint32_t)((ks * 16 + v_r) * 128 + d4 * 32 + v_cb));
                LDSM_X4_T(vh[d4], sVh + off);
                LDSM_X4_T(vl[d4], sVl + off);
            }
            #pragma unroll
            for (int mt = 0; mt < 2; mt++) {
                float a0 = s[mt][2 * ks][0],     a1 = s[mt][2 * ks][1];
                float a2 = s[mt][2 * ks][2],     a3 = s[mt][2 * ks][3];
                float c0 = s[mt][2 * ks + 1][0], c1 = s[mt][2 * ks + 1][1];
                float c2 = s[mt][2 * ks + 1][2], c3 = s[mt][2 * ks + 1][3];
                uint32_t pah[4], pal[4];
                pah[0] = packbf(a0, a1); pah[1] = packbf(a2, a3);
                pah[2] = packbf(c0, c1); pah[3] = packbf(c2, c3);
                pal[0] = packbf(bfres(a0), bfres(a1)); pal[1] = packbf(bfres(a2), bfres(a3));
                pal[2] = packbf(bfres(c0), bfres(c1)); pal[3] = packbf(bfres(c2), bfres(c3));
                #pragma unroll
                for (int nt = 0; nt < 8; nt++) {
                    const uint32_t* Bh = &vh[nt >> 1][(nt & 1) * 2];
                    const uint32_t* Bl = &vl[nt >> 1][(nt & 1) * 2];
                    mma16816(o[mt][nt], pah, Bh);
                    mma16816(o[mt][nt], pah, Bl);
                    mma16816(o[mt][nt], pal, Bh);
                }
            }
        }
    }

    #pragma unroll
    for (int mt = 0; mt < 2; mt++)
        #pragma unroll
        for (int rh = 0; rh < 2; rh++) {
            float inv = 1.0f / lst[mt][rh];
            int row = q0 + wm + mt * 16 + rh * 8 + rl;
            #pragma unroll
            for (int nt = 0; nt < 8; nt++) {
                float v0 = o[mt][nt][rh * 2]     * inv;
                float v1 = o[mt][nt][rh * 2 + 1] * inv;
                size_t idx = (size_t)row * NHID + qcol + nt * 8 + kp;
                *(uint32_t*)(Ch + idx) = packbf(v0, v1);
                *(uint32_t*)(Cl + idx) = packbf(bfres(v0), bfres(v1));
            }
        }
}

// ---------------------------------------------------------------------------
// out = LayerNorm(inception + attended)
// ---------------------------------------------------------------------------
__global__ __launch_bounds__(256) void add_ln_kernel(
    const float* __restrict__ inc, const float* __restrict__ y,
    const float* __restrict__ gamma, const float* __restrict__ beta,
    float* __restrict__ out)
{
    const int row = blockIdx.x;
    const int tid = threadIdx.x;
    const size_t base = (size_t)row * NHID;

    float v = inc[base + tid] + y[base + tid];

    float s1 = v, s2 = v * v;
    #pragma unroll
    for (int o = 16; o; o >>= 1) {
        s1 += __shfl_xor_sync(0xFFFFFFFFu, s1, o);
        s2 += __shfl_xor_sync(0xFFFFFFFFu, s2, o);
    }
    __shared__ float r1[8], r2[8];
    if ((tid & 31) == 0) { r1[tid >> 5] = s1; r2[tid >> 5] = s2; }
    __syncthreads();
    float t1 = 0.f, t2 = 0.f;
    #pragma unroll
    for (int i = 0; i < 8; i++) { t1 += r1[i]; t2 += r2[i]; }

    float mu  = t1 * (1.0f / NHID);
    float var = t2 * (1.0f / NHID) - mu * mu;
    float rs  = rsqrtf(var + 1e-5f);
    out[base + tid] = (v - mu) * rs * gamma[tid] + beta[tid];
}

// ---------------------------------------------------------------------------
// Launch
// ---------------------------------------------------------------------------
extern "C" void kernel_launch(void* const* d_in, const int* in_sizes, int n_in,
                              void* d_out, int out_size)
{
    const float* x     = (const float*)d_in[0];
    const float* ea1   = (const float*)d_in[1];
    const float* ea2   = (const float*)d_in[2];
    const float* ln_w  = (const float*)d_in[3];
    const float* w1    = (const float*)d_in[4];
    const float* w2    = (const float*)d_in[5];
    const float* inw   = (const float*)d_in[6];   // [768,256] = [N,K]
    const float* inb   = (const float*)d_in[7];
    const float* outw  = (const float*)d_in[8];   // [256,256] = [N,K]
    const float* outb  = (const float*)d_in[9];
    const float* gamma = (const float*)d_in[10];
    const float* beta  = (const float*)d_in[11];
    const int*   ei1   = (const int*)d_in[12];
    const int*   ei2   = (const int*)d_in[13];
    float* out = (float*)d_out;

    const int n_edges = in_sizes[1];

    float *p_h, *p_inc, *p_y;
    __nv_bfloat16 *p_xhi, *p_xlo, *p_ahi, *p_alo, *p_wchi, *p_wclo;
    __nv_bfloat16 *p_wqhi, *p_wqlo, *p_wohi, *p_wolo, *p_qkvh, *p_qkvl;
    cudaGetSymbolAddress((void**)&p_h, g_h);
    cudaGetSymbolAddress((void**)&p_inc, g_inc);
    cudaGetSymbolAddress((void**)&p_y, g_y);
    cudaGetSymbolAddress((void**)&p_xhi, g_xhi);
    cudaGetSymbolAddress((void**)&p_xlo, g_xlo);
    cudaGetSymbolAddress((void**)&p_ahi, g_ahi);
    cudaGetSymbolAddress((void**)&p_alo, g_alo);
    cudaGetSymbolAddress((void**)&p_wchi, g_wcathi);
    cudaGetSymbolAddress((void**)&p_wclo, g_wcatlo);
    cudaGetSymbolAddress((void**)&p_wqhi, g_wqhi);
    cudaGetSymbolAddress((void**)&p_wqlo, g_wqlo);
    cudaGetSymbolAddress((void**)&p_wohi, g_wohi);
    cudaGetSymbolAddress((void**)&p_wolo, g_wolo);
    cudaGetSymbolAddress((void**)&p_qkvh, g_qkvh);
    cudaGetSymbolAddress((void**)&p_qkvl, g_qkvl);

    cudaFuncSetAttribute(hmma_gemm, cudaFuncAttributeMaxDynamicSharedMemorySize, SMEM_TOTAL);

    // CSR bucket build
    zero_cnt_kernel<<<(N_NODES + 255) / 256, 256>>>();
    build_csr<<<(n_edges + 255) / 256, 256>>>(ei1, ea1, n_edges, 0);
    build_csr<<<(n_edges + 255) / 256, 256>>>(ei2, ea2, n_edges, 1);

    // x -> hi/lo ; concat conv weights^T -> hi/lo
    cvt_hilo4<<<(N_NODES * NFEAT / 4 + 255) / 256, 256>>>(x, p_xhi, p_xlo, N_NODES * NFEAT / 4);
    cvt_hilo_T<<<(NFEAT * NHID + 255) / 256, 256>>>(ln_w, p_wchi, p_wclo, NFEAT, NHID);
    cvt_hilo_T<<<(NFEAT * NHID + 255) / 256, 256>>>(w1, p_wchi + 256 * NFEAT,
                                                    p_wclo + 256 * NFEAT, NFEAT, NHID);
    cvt_hilo_T<<<(NFEAT * NHID + 255) / 256, 256>>>(w2, p_wchi + 512 * NFEAT,
                                                    p_wclo + 512 * NFEAT, NFEAT, NHID);

    // One fused conv GEMM: [x0 | h1 | h2] = x @ [ln_w | w1 | w2]
    dim3 gH(HCAT / 128, N_NODES / 64);
    hmma_gemm<<<gH, 256, SMEM_TOTAL>>>(p_xhi, p_xlo, p_wchi, p_wclo, nullptr,
                                       p_h, nullptr, nullptr, N_NODES, HCAT, NFEAT);

    // Pull-side gather: inception fp32 + hi/lo bf16
    gather_kernel<<<N_NODES, 256>>>(p_h, p_inc, p_ahi, p_alo);

    // qkv = inc @ in_proj_w^T + b  -> bf16 hi/lo directly
    cvt_hilo4<<<(QKVDIM * NHID / 4 + 255) / 256, 256>>>(inw, p_wqhi, p_wqlo, QKVDIM * NHID / 4);
    dim3 gQ(QKVDIM / 128, N_NODES / 64);
    hmma_gemm<<<gQ, 256, SMEM_TOTAL>>>(p_ahi, p_alo, p_wqhi, p_wqlo, inb,
                                       nullptr, p_qkvh, p_qkvl, N_NODES, QKVDIM, NHID);

    // attention -> ctx hi/lo (overwrites ahi/alo)
    dim3 gAtt(NPG / 128, HEADS, NGRAPHS);
    attn_mma<<<gAtt, 128>>>(p_qkvh, p_qkvl, p_ahi, p_alo);

    // y = ctx @ out_proj_w^T + b
    dim3 gA(NHID / 128, N_NODES / 64);
    cvt_hilo4<<<(NHID * NHID / 4 + 255) / 256, 256>>>(outw, p_wohi, p_wolo, NHID * NHID / 4);
    hmma_gemm<<<gA, 256, SMEM_TOTAL>>>(p_ahi, p_alo, p_wohi, p_wolo, outb,
                                       p_y, nullptr, nullptr, N_NODES, NHID, NHID);

    // out = LN(inc + y)
    add_ln_kernel<<<N_NODES, 256>>>(p_inc, p_y, gamma, beta, out);
}